// round 11
// baseline (speedup 1.0000x reference)
#include <cuda_runtime.h>
#include <cuda_bf16.h>

#define BATCH 256
#define L 256
#define D 64
#define NST 24
#define CPROJ 72   // DT_RANK + 2*NST

typedef unsigned long long u64;

// ---------------- scratch ----------------------------------------------------
__device__ float g_xconv[BATCH * 4 * 64 * 64];  // (b,c,h,w)
__device__ float g_xt[BATCH * L * D];           // (b,l,d)
__device__ float g_dtr[BATCH * 4 * NST * L];    // (b,k,r,l)
__device__ float g_bc[BATCH * 4 * 48 * L];      // (b,k,j,l)  j:0..23=B, 24..47=C
__device__ float g_ysum[BATCH * L * D];         // combined y (b,l,d)
// two-pass scan buffers: ((kb*4+c)*24+n)*64+d  (hz/pr chunks 0..2, hin 0..3)
__device__ float g_hz[BATCH * 4 * 4 * NST * 64];
__device__ float g_pr[BATCH * 4 * 4 * NST * 64];
__device__ float g_hin[BATCH * 4 * 4 * NST * 64];

__device__ __forceinline__ int map_l(int k, int l) {
    int lm = (k & 2) ? (255 - l) : l;
    if (k & 1) lm = ((lm & 15) << 4) | (lm >> 4);
    return lm;
}
__device__ __forceinline__ float silu(float x) { return x / (1.f + __expf(-x)); }

__device__ __forceinline__ u64 pk2(float lo, float hi) {
    u64 r; asm("mov.b64 %0,{%1,%2};" : "=l"(r) : "f"(lo), "f"(hi)); return r;
}
__device__ __forceinline__ void unpk2(float& lo, float& hi, u64 v) {
    asm("mov.b64 {%0,%1},%2;" : "=f"(lo), "=f"(hi) : "l"(v));
}
__device__ __forceinline__ u64 mul2(u64 a, u64 b) {
    u64 r; asm("mul.rn.f32x2 %0,%1,%2;" : "=l"(r) : "l"(a), "l"(b)); return r;
}
__device__ __forceinline__ u64 fma2(u64 a, u64 b, u64 c) {
    u64 r; asm("fma.rn.f32x2 %0,%1,%2,%3;" : "=l"(r) : "l"(a), "l"(b), "l"(c)); return r;
}
__device__ __forceinline__ unsigned f2tf(float f) {
    unsigned u; asm("cvt.rna.tf32.f32 %0,%1;" : "=r"(u) : "f"(f)); return u;
}
__device__ __forceinline__ void mma_tf32(float c[4],
                                         unsigned a0, unsigned a1, unsigned a2, unsigned a3,
                                         unsigned b0, unsigned b1) {
    asm volatile(
        "mma.sync.aligned.m16n8k8.row.col.f32.tf32.tf32.f32 "
        "{%0,%1,%2,%3},{%4,%5,%6,%7},{%8,%9},{%0,%1,%2,%3};"
        : "+f"(c[0]), "+f"(c[1]), "+f"(c[2]), "+f"(c[3])
        : "r"(a0), "r"(a1), "r"(a2), "r"(a3), "r"(b0), "r"(b1));
}

// ---------------- K2a: depthwise conv ----------------------------------------
__global__ void __launch_bounds__(256) k_dwconv(const float* __restrict__ xin,
                                                const float* __restrict__ cw,
                                                const float* __restrict__ cb,
                                                float* __restrict__ xc) {
    __shared__ float ts[66][68];
    int bc_ = blockIdx.x;
    int c = bc_ & 3, b = bc_ >> 2;
    int t = threadIdx.x;
    for (int i = t; i < 66 * 68; i += 256) ((float*)ts)[i] = 0.f;
    __syncthreads();
    const float* xb = xin + b * 16 * 16 * 64 + c * 16;
#pragma unroll
    for (int it = 0; it < 16; it++) {
        int e = it * 256 + t;
        int pq = e >> 4, ij = e & 15;
        int p = pq >> 4, q = pq & 15;
        int i2 = ij >> 2, j2 = ij & 3;
        ts[1 + p * 4 + i2][1 + q * 4 + j2] = xb[pq * 64 + ij];
    }
    __syncthreads();
    float wr[9];
#pragma unroll
    for (int i = 0; i < 9; i++) wr[i] = __ldg(&cw[c * 9 + i]);
    float cbv = __ldg(&cb[c]);
    int h = t >> 2, wq = t & 3;
    float* op = xc + (bc_ * 64 + h) * 64 + wq * 16;
#pragma unroll
    for (int j = 0; j < 16; j++) {
        int wcol = wq * 16 + j;
        float acc = cbv;
#pragma unroll
        for (int di = 0; di < 3; di++)
#pragma unroll
            for (int dj = 0; dj < 3; dj++)
                acc += ts[h + di][wcol + dj] * wr[di * 3 + dj];
        op[j] = silu(acc);
    }
}

// ---------------- K2b: patch conv + BN ---------------------------------------
__global__ void __launch_bounds__(512) k_patch(const float* __restrict__ xc,
                                               const float* __restrict__ pw,
                                               const float* __restrict__ pb,
                                               const float* __restrict__ gam,
                                               const float* __restrict__ bet,
                                               const float* __restrict__ mn,
                                               const float* __restrict__ vr,
                                               float* __restrict__ xt) {
    __shared__ __align__(16) float ws[64 * 65];
    __shared__ __align__(16) float px[64][64];
    int b = blockIdx.y, lg = blockIdx.x;
    int e = threadIdx.x, li = threadIdx.y;
    int t = li * 64 + e;
    for (int i = t; i < 4096; i += 512) ws[(i & 63) * 65 + (i >> 6)] = pw[i];
    for (int i = t; i < 4096; i += 512) {
        int row = i >> 6, m = i & 63;
        int l = lg * 64 + row;
        int ph = l >> 4, pwd = l & 15;
        int c = m >> 4, ij = m & 15, i2 = ij >> 2, j2 = ij & 3;
        px[row][m] = xc[((b * 4 + c) * 64 + ph * 4 + i2) * 64 + pwd * 4 + j2];
    }
    __syncthreads();
    float acc[8];
#pragma unroll
    for (int j = 0; j < 8; j++) acc[j] = 0.f;
    int r0 = li * 8;
#pragma unroll
    for (int m4 = 0; m4 < 16; m4++) {
        float4 xv[8];
#pragma unroll
        for (int j = 0; j < 8; j++) xv[j] = ((const float4*)px[r0 + j])[m4];
#pragma unroll
        for (int dd = 0; dd < 4; dd++) {
            float wv = ws[(m4 * 4 + dd) * 65 + e];
#pragma unroll
            for (int j = 0; j < 8; j++) {
                float v = dd == 0 ? xv[j].x : dd == 1 ? xv[j].y : dd == 2 ? xv[j].z : xv[j].w;
                acc[j] += v * wv;
            }
        }
    }
    float sc = __ldg(&gam[e]) * rsqrtf(__ldg(&vr[e]) + 1e-5f);
    float pbv = __ldg(&pb[e]), mnv = __ldg(&mn[e]), btv = __ldg(&bet[e]);
#pragma unroll
    for (int j = 0; j < 8; j++)
        xt[(b * 256 + lg * 64 + r0 + j) * 64 + e] = (acc[j] + pbv - mnv) * sc + btv;
}

// ---------------- K3: x_dbl projection via tf32 mma, 2 CTAs per (k,b) --------
#define AS_STRIDE 136
#define BS_STRIDE 72
__global__ void __launch_bounds__(256, 3) k_proj(const float* __restrict__ xt,
                                                 const float* __restrict__ xpw,
                                                 float* __restrict__ dtrg,
                                                 float* __restrict__ bc) {
    extern __shared__ unsigned sm[];
    unsigned* As = sm;
    unsigned* Bs = sm + 64 * AS_STRIDE;
    int kh = blockIdx.x, b = blockIdx.y;
    int k = kh & 3, half = kh >> 2;
    int t = threadIdx.x, w = t >> 5, lane = t & 31;
    int gid = lane >> 2, tig = lane & 3;
    const float* wk = xpw + k * CPROJ * 64;

    for (int i = t; i < CPROJ * 64; i += 256) {
        int c = i >> 6, kk = i & 63;
        Bs[kk * BS_STRIDE + c] = f2tf(wk[i]);
    }
    {
        int lr = t >> 1;
        int kk0 = (t & 1) * 32;
        int lm = map_l(k, half * 128 + lr);
        const float4* xp = (const float4*)(xt + (b * 256 + lm) * 64 + kk0);
#pragma unroll
        for (int j4 = 0; j4 < 8; j4++) {
            float4 v = __ldg(xp + j4);
            As[(kk0 + 4 * j4 + 0) * AS_STRIDE + lr] = f2tf(v.x);
            As[(kk0 + 4 * j4 + 1) * AS_STRIDE + lr] = f2tf(v.y);
            As[(kk0 + 4 * j4 + 2) * AS_STRIDE + lr] = f2tf(v.z);
            As[(kk0 + 4 * j4 + 3) * AS_STRIDE + lr] = f2tf(v.w);
        }
    }
    __syncthreads();

    int r0 = w * 16;
    unsigned a[8][4];
#pragma unroll
    for (int ks = 0; ks < 8; ks++) {
        int kb = ks * 8;
        a[ks][0] = As[(kb + tig) * AS_STRIDE + r0 + gid];
        a[ks][1] = As[(kb + tig) * AS_STRIDE + r0 + gid + 8];
        a[ks][2] = As[(kb + tig + 4) * AS_STRIDE + r0 + gid];
        a[ks][3] = As[(kb + tig + 4) * AS_STRIDE + r0 + gid + 8];
    }

    float* dto = dtrg + (b * 4 + k) * NST * 256;
    float* bco = bc + (b * 4 + k) * 48 * 256;
    int rg = half * 128 + r0 + gid;
#pragma unroll
    for (int n = 0; n < 9; n++) {
        float acc[4] = {0.f, 0.f, 0.f, 0.f};
#pragma unroll
        for (int ks = 0; ks < 8; ks++) {
            int kb = ks * 8;
            unsigned b0 = Bs[(kb + tig) * BS_STRIDE + n * 8 + gid];
            unsigned b1 = Bs[(kb + tig + 4) * BS_STRIDE + n * 8 + gid];
            mma_tf32(acc, a[ks][0], a[ks][1], a[ks][2], a[ks][3], b0, b1);
        }
        int c0 = n * 8 + 2 * tig;
#pragma unroll
        for (int q = 0; q < 2; q++) {
            int c = c0 + q;
            float* base = (c < 24) ? (dto + c * 256) : (bco + (c - 24) * 256);
            base[rg]     = acc[q];
            base[rg + 8] = acc[q + 2];
        }
    }
}
#define PROJ_SMEM ((64 * AS_STRIDE + 64 * BS_STRIDE) * 4)

// ---------------- K4a: scan pass 1 (chunks 0..2, states only, low-reg) --------
// grid (12, B): k = bid.x & 3, c = bid.x >> 2 (0..2). block 64.
__global__ void __launch_bounds__(64, 10) k_scan1(const float* __restrict__ xt,
                                                  const float* __restrict__ dtrg,
                                                  const float* __restrict__ bc,
                                                  const float* __restrict__ dtw_g,
                                                  const float* __restrict__ alog,
                                                  const float* __restrict__ dbias,
                                                  float* __restrict__ hz,
                                                  float* __restrict__ pr) {
    __shared__ __align__(16) float sbcB[16][24];
    __shared__ __align__(16) float sdtr[NST * 16];
    __shared__ float su[16][64];
    __shared__ float sdtw[NST * 64];   // [r][d]
    int kc = blockIdx.x, b = blockIdx.y;
    int k = kc & 3, c = kc >> 2;
    int d = threadIdx.x;
    int kd = k * 64 + d;

    // stage dt weights: sdtw[r*64+d]
    {
        const float4* dwp = (const float4*)(dtw_g + kd * NST);
#pragma unroll
        for (int i = 0; i < 6; i++) {
            float4 v = __ldg(dwp + i);
            sdtw[(4 * i + 0) * 64 + d] = v.x;
            sdtw[(4 * i + 1) * 64 + d] = v.y;
            sdtw[(4 * i + 2) * 64 + d] = v.z;
            sdtw[(4 * i + 3) * 64 + d] = v.w;
        }
    }
    float a0 = -__expf(__ldg(&alog[kd * NST]));
    bool chain = (a0 != 0.f);
#pragma unroll
    for (int n = 1; n < NST; n++) {
        float an = -__expf(__ldg(&alog[kd * NST + n]));
        chain = chain && (fabsf(an - (float)(n + 1) * a0) <= 1e-4f * fabsf(an));
    }
    float bias = __ldg(&dbias[kd]);
    int kb = b * 4 + k;
    const float* dtrp = dtrg + kb * NST * 256;
    const float* bcp = bc + kb * 48 * 256;
    const float* xrow = xt + b * 256 * 64;
    int outb = (kb * 4 + c) * NST;
    int lstart = c * 64;

    u64 h2[12];
#pragma unroll
    for (int p = 0; p < 12; p++) h2[p] = 0ull;
    float sumd = 0.f;

    int chainU = __syncthreads_and(chain ? 1 : 0);

    if (chainU) {
        for (int l0 = lstart; l0 < lstart + 64; l0 += 16) {
            __syncthreads();
#pragma unroll
            for (int m = 0; m < 6; m++) {
                int idx = d * 6 + m;
                sbcB[idx & 15][idx >> 4] = bcp[(idx >> 4) * 256 + l0 + (idx & 15)];
            }
#pragma unroll
            for (int m = 0; m < 6; m++) {
                int idx = d * 6 + m;
                sdtr[idx] = dtrp[(idx >> 4) * 256 + l0 + (idx & 15)];
            }
#pragma unroll
            for (int i = 0; i < 16; i++)
                su[i][d] = __ldg(&xrow[map_l(k, l0 + i) * 64 + d]);
            __syncthreads();
            float dtc[16];
            {
                u64 dt2[8];
#pragma unroll
                for (int ip = 0; ip < 8; ip++) dt2[ip] = 0ull;
#pragma unroll
                for (int r = 0; r < NST; r++) {
                    float wv = sdtw[r * 64 + d];
                    u64 wp = pk2(wv, wv);
#pragma unroll
                    for (int q = 0; q < 4; q++) {
                        ulonglong2 v = *(const ulonglong2*)&sdtr[r * 16 + 4 * q];
                        dt2[2 * q]     = fma2(wp, v.x, dt2[2 * q]);
                        dt2[2 * q + 1] = fma2(wp, v.y, dt2[2 * q + 1]);
                    }
                }
#pragma unroll
                for (int ip = 0; ip < 8; ip++) unpk2(dtc[2 * ip], dtc[2 * ip + 1], dt2[ip]);
            }
#pragma unroll 2
            for (int i = 0; i < 16; i++) {
                float xv = dtc[i] + bias;
                float delta = (xv > 15.f) ? xv : __logf(1.f + __expf(xv));
                sumd += delta;
                float u = su[i][d];
                float du = delta * u;
                float q = __expf(delta * a0);
                float q2s = q * q;
                u64 dA = pk2(q, q2s);
                u64 qq = pk2(q2s, q2s);
                u64 du2 = pk2(du, du);
#pragma unroll
                for (int p = 0; p < 12; p++) {
                    u64 B2 = *(const u64*)&sbcB[i][2 * p];
                    h2[p] = fma2(dA, h2[p], mul2(du2, B2));
                    if (p < 11) dA = mul2(dA, qq);
                }
            }
        }
        float qt = __expf(a0 * sumd);
        float t2 = qt * qt;
        u64 dA = pk2(qt, t2);
        u64 qq = pk2(t2, t2);
#pragma unroll
        for (int p = 0; p < 12; p++) {
            float lo, hi; unpk2(lo, hi, dA);
            pr[(outb + 2 * p) * 64 + d] = lo;
            pr[(outb + 2 * p + 1) * 64 + d] = hi;
            if (p < 11) dA = mul2(dA, qq);
        }
    } else {
        float afl[12], afh[12];
#pragma unroll
        for (int p = 0; p < 12; p++) {
            afl[p] = -__expf(__ldg(&alog[kd * NST + 2 * p]));
            afh[p] = -__expf(__ldg(&alog[kd * NST + 2 * p + 1]));
        }
        u64 pr2[12];
#pragma unroll
        for (int p = 0; p < 12; p++) pr2[p] = pk2(1.f, 1.f);
        for (int l0 = lstart; l0 < lstart + 64; l0 += 16) {
            __syncthreads();
#pragma unroll
            for (int m = 0; m < 6; m++) {
                int idx = d * 6 + m;
                sbcB[idx & 15][idx >> 4] = bcp[(idx >> 4) * 256 + l0 + (idx & 15)];
            }
#pragma unroll
            for (int m = 0; m < 6; m++) {
                int idx = d * 6 + m;
                sdtr[idx] = dtrp[(idx >> 4) * 256 + l0 + (idx & 15)];
            }
#pragma unroll
            for (int i = 0; i < 16; i++)
                su[i][d] = __ldg(&xrow[map_l(k, l0 + i) * 64 + d]);
            __syncthreads();
            float dtc[16];
            {
                u64 dt2[8];
#pragma unroll
                for (int ip = 0; ip < 8; ip++) dt2[ip] = 0ull;
#pragma unroll
                for (int r = 0; r < NST; r++) {
                    float wv = sdtw[r * 64 + d];
                    u64 wp = pk2(wv, wv);
#pragma unroll
                    for (int q = 0; q < 4; q++) {
                        ulonglong2 v = *(const ulonglong2*)&sdtr[r * 16 + 4 * q];
                        dt2[2 * q]     = fma2(wp, v.x, dt2[2 * q]);
                        dt2[2 * q + 1] = fma2(wp, v.y, dt2[2 * q + 1]);
                    }
                }
#pragma unroll
                for (int ip = 0; ip < 8; ip++) unpk2(dtc[2 * ip], dtc[2 * ip + 1], dt2[ip]);
            }
#pragma unroll 1
            for (int i = 0; i < 16; i++) {
                float xv = dtc[i] + bias;
                float delta = (xv > 15.f) ? xv : __logf(1.f + __expf(xv));
                float u = su[i][d];
                float du = delta * u;
                u64 du2 = pk2(du, du);
#pragma unroll
                for (int p = 0; p < 12; p++) {
                    u64 dA = pk2(__expf(delta * afl[p]), __expf(delta * afh[p]));
                    u64 B2 = *(const u64*)&sbcB[i][2 * p];
                    h2[p] = fma2(dA, h2[p], mul2(du2, B2));
                    pr2[p] = mul2(pr2[p], dA);
                }
            }
        }
#pragma unroll
        for (int p = 0; p < 12; p++) {
            float lo, hi; unpk2(lo, hi, pr2[p]);
            pr[(outb + 2 * p) * 64 + d] = lo;
            pr[(outb + 2 * p + 1) * 64 + d] = hi;
        }
    }
#pragma unroll
    for (int p = 0; p < 12; p++) {
        float lo, hi; unpk2(lo, hi, h2[p]);
        hz[(outb + 2 * p) * 64 + d] = lo;
        hz[(outb + 2 * p + 1) * 64 + d] = hi;
    }
}

// ---------------- K4b: sequential chunk combine -------------------------------
__global__ void __launch_bounds__(64) k_comb(const float* __restrict__ hz,
                                             const float* __restrict__ pr,
                                             float* __restrict__ hin) {
    int k = blockIdx.x, b = blockIdx.y, d = threadIdx.x;
    int kb = b * 4 + k;
    float h[NST];
#pragma unroll
    for (int n = 0; n < NST; n++) h[n] = 0.f;
#pragma unroll
    for (int c = 0; c < 4; c++) {
        int ob = (kb * 4 + c) * NST;
#pragma unroll
        for (int n = 0; n < NST; n++) {
            hin[(ob + n) * 64 + d] = h[n];
            if (c < 3)
                h[n] = pr[(ob + n) * 64 + d] * h[n] + hz[(ob + n) * 64 + d];
        }
    }
}

// ---------------- K4c: scan pass 2 (4 chunks, h_in init, low-reg) -------------
// grid (16, B): k = bid.x & 3, c = bid.x >> 2. block 64.
__global__ void __launch_bounds__(64, 10) k_scan2(const float* __restrict__ xt,
                                                  const float* __restrict__ dtrg,
                                                  const float* __restrict__ bc,
                                                  const float* __restrict__ dtw_g,
                                                  const float* __restrict__ alog,
                                                  const float* __restrict__ dbias,
                                                  const float* __restrict__ Dsv,
                                                  const float* __restrict__ hin,
                                                  float* __restrict__ ysum) {
    __shared__ __align__(16) float sbc[16][48];
    __shared__ __align__(16) float sdtr[NST * 16];
    __shared__ float su[16][64];
    __shared__ float sdtw[NST * 64];
    int kc = blockIdx.x, b = blockIdx.y;
    int k = kc & 3, c = kc >> 2;
    int d = threadIdx.x;
    int kd = k * 64 + d;

    {
        const float4* dwp = (const float4*)(dtw_g + kd * NST);
#pragma unroll
        for (int i = 0; i < 6; i++) {
            float4 v = __ldg(dwp + i);
            sdtw[(4 * i + 0) * 64 + d] = v.x;
            sdtw[(4 * i + 1) * 64 + d] = v.y;
            sdtw[(4 * i + 2) * 64 + d] = v.z;
            sdtw[(4 * i + 3) * 64 + d] = v.w;
        }
    }
    float a0 = -__expf(__ldg(&alog[kd * NST]));
    bool chain = (a0 != 0.f);
#pragma unroll
    for (int n = 1; n < NST; n++) {
        float an = -__expf(__ldg(&alog[kd * NST + n]));
        chain = chain && (fabsf(an - (float)(n + 1) * a0) <= 1e-4f * fabsf(an));
    }
    float bias = __ldg(&dbias[kd]);
    float Dv = __ldg(&Dsv[kd]);
    int kb = b * 4 + k;
    const float* dtrp = dtrg + kb * NST * 256;
    const float* bcp = bc + kb * 48 * 256;
    const float* xrow = xt + b * 256 * 64;
    float* yb = ysum + b * 256 * 64;
    int outb = (kb * 4 + c) * NST;
    int lstart = c * 64;

    u64 h2[12];
#pragma unroll
    for (int p = 0; p < 12; p++)
        h2[p] = pk2(hin[(outb + 2 * p) * 64 + d], hin[(outb + 2 * p + 1) * 64 + d]);

    int chainU = __syncthreads_and(chain ? 1 : 0);

    for (int l0 = lstart; l0 < lstart + 64; l0 += 16) {
        __syncthreads();
#pragma unroll
        for (int m = 0; m < 12; m++) {
            int idx = d * 12 + m;
            sbc[idx & 15][idx >> 4] = bcp[(idx >> 4) * 256 + l0 + (idx & 15)];
        }
#pragma unroll
        for (int m = 0; m < 6; m++) {
            int idx = d * 6 + m;
            sdtr[idx] = dtrp[(idx >> 4) * 256 + l0 + (idx & 15)];
        }
#pragma unroll
        for (int i = 0; i < 16; i++)
            su[i][d] = __ldg(&xrow[map_l(k, l0 + i) * 64 + d]);
        __syncthreads();

        float dtc[16];
        {
            u64 dt2[8];
#pragma unroll
            for (int ip = 0; ip < 8; ip++) dt2[ip] = 0ull;
#pragma unroll
            for (int r = 0; r < NST; r++) {
                float wv = sdtw[r * 64 + d];
                u64 wp = pk2(wv, wv);
#pragma unroll
                for (int q = 0; q < 4; q++) {
                    ulonglong2 v = *(const ulonglong2*)&sdtr[r * 16 + 4 * q];
                    dt2[2 * q]     = fma2(wp, v.x, dt2[2 * q]);
                    dt2[2 * q + 1] = fma2(wp, v.y, dt2[2 * q + 1]);
                }
            }
#pragma unroll
            for (int ip = 0; ip < 8; ip++) unpk2(dtc[2 * ip], dtc[2 * ip + 1], dt2[ip]);
        }

        if (chainU) {
#pragma unroll 2
            for (int i = 0; i < 16; i++) {
                int l = l0 + i;
                float xv = dtc[i] + bias;
                float delta = (xv > 15.f) ? xv : __logf(1.f + __expf(xv));
                float u = su[i][d];
                float du = delta * u;
                float q = __expf(delta * a0);
                float q2s = q * q;
                u64 dA = pk2(q, q2s);
                u64 qq = pk2(q2s, q2s);
                u64 du2 = pk2(du, du);
                u64 y2a = 0ull, y2b = 0ull;
#pragma unroll
                for (int p = 0; p < 12; p++) {
                    u64 B2 = *(const u64*)&sbc[i][2 * p];
                    u64 C2 = *(const u64*)&sbc[i][24 + 2 * p];
                    h2[p] = fma2(dA, h2[p], mul2(du2, B2));
                    if (p & 1) y2b = fma2(h2[p], C2, y2b);
                    else       y2a = fma2(h2[p], C2, y2a);
                    if (p < 11) dA = mul2(dA, qq);
                }
                float ylo, yhi, zlo, zhi;
                unpk2(ylo, yhi, y2a); unpk2(zlo, zhi, y2b);
                atomicAdd(&yb[map_l(k, l) * 64 + d], ylo + yhi + zlo + zhi + Dv * u);
            }
        } else {
#pragma unroll 1
            for (int i = 0; i < 16; i++) {
                int l = l0 + i;
                float xv = dtc[i] + bias;
                float delta = (xv > 15.f) ? xv : __logf(1.f + __expf(xv));
                float u = su[i][d];
                float du = delta * u;
                u64 du2 = pk2(du, du);
                u64 y2 = 0ull;
#pragma unroll
                for (int p = 0; p < 12; p++) {
                    float alo = -__expf(__ldg(&alog[kd * NST + 2 * p]));
                    float ahi = -__expf(__ldg(&alog[kd * NST + 2 * p + 1]));
                    u64 dA = pk2(__expf(delta * alo), __expf(delta * ahi));
                    u64 B2 = *(const u64*)&sbc[i][2 * p];
                    u64 C2 = *(const u64*)&sbc[i][24 + 2 * p];
                    h2[p] = fma2(dA, h2[p], mul2(du2, B2));
                    y2 = fma2(h2[p], C2, y2);
                }
                float ylo, yhi;
                unpk2(ylo, yhi, y2);
                atomicAdd(&yb[map_l(k, l) * 64 + d], ylo + yhi + Dv * u);
            }
        }
    }
}

// ---------------- K5: LN + inline z-gate + out_proj, 2 CTAs per b ------------
__global__ void __launch_bounds__(128) k_final(const float* __restrict__ xin,
                                               const float* __restrict__ ysum,
                                               const float* __restrict__ ipw,
                                               const float* __restrict__ lng,
                                               const float* __restrict__ lnb,
                                               const float* __restrict__ wo,
                                               float* __restrict__ out) {
    __shared__ __align__(16) float wsI[64 * 64];
    __shared__ __align__(16) float wsO[64 * 64];
    __shared__ float gs[64], bs[64];
    int b = blockIdx.y, half = blockIdx.x;
    int tid = threadIdx.x;
    int l = half * 128 + tid;
    for (int i = tid; i < 4096; i += 128) { wsI[i] = ipw[i]; wsO[i] = wo[i]; }
    if (tid < 64) { gs[tid] = lng[tid]; bs[tid] = lnb[tid]; }
    __syncthreads();

    float yv[64];
    u64 xr2[32];
    float mu = 0.f;
    {
        const float4* yp = (const float4*)(ysum + (b * 256 + l) * 64);
        const float4* xp = (const float4*)(xin + (b * 256 + l) * 64);
#pragma unroll
        for (int i = 0; i < 16; i++) {
            float4 v = yp[i];
            yv[4 * i + 0] = v.x; yv[4 * i + 1] = v.y;
            yv[4 * i + 2] = v.z; yv[4 * i + 3] = v.w;
            mu += v.x + v.y + v.z + v.w;
            float4 x = xp[i];
            xr2[2 * i]     = pk2(x.x, x.y);
            xr2[2 * i + 1] = pk2(x.z, x.w);
        }
    }
    mu *= (1.f / 64.f);
    float var = 0.f;
#pragma unroll
    for (int e = 0; e < 64; e++) { float tv = yv[e] - mu; var += tv * tv; }
    var *= (1.f / 64.f);
    float rs = rsqrtf(var + 1e-5f);

    u64 g2[32];
#pragma unroll
    for (int e2 = 0; e2 < 32; e2++) {
        float ge[2];
#pragma unroll
        for (int hh = 0; hh < 2; hh++) {
            int e = 2 * e2 + hh;
            const u64* wrow = (const u64*)&wsI[e * 64];
            u64 acc = 0ull;
#pragma unroll
            for (int j = 0; j < 32; j++) acc = fma2(xr2[j], wrow[j], acc);
            float lo, hi; unpk2(lo, hi, acc);
            float zv = silu(lo + hi);
            ge[hh] = ((yv[e] - mu) * rs * gs[e] + bs[e]) * zv;
        }
        g2[e2] = pk2(ge[0], ge[1]);
    }

    float4* op = (float4*)(out + (b * 256 + l) * 64);
#pragma unroll 1
    for (int dg = 0; dg < 16; dg++) {
        float res[4];
#pragma unroll
        for (int q = 0; q < 4; q++) {
            const u64* wrow = (const u64*)&wsO[(dg * 4 + q) * 64];
            u64 acc = 0ull;
#pragma unroll
            for (int j = 0; j < 32; j++) acc = fma2(g2[j], wrow[j], acc);
            float lo, hi; unpk2(lo, hi, acc);
            res[q] = lo + hi;
        }
        op[dg] = make_float4(res[0], res[1], res[2], res[3]);
    }
}

// ---------------- launch ------------------------------------------------------
extern "C" void kernel_launch(void* const* d_in, const int* in_sizes, int n_in,
                              void* d_out, int out_size) {
    const float* x_in   = (const float*)d_in[0];
    const float* ipw    = (const float*)d_in[1];
    const float* conv_w = (const float*)d_in[2];
    const float* conv_b = (const float*)d_in[3];
    const float* patch_w= (const float*)d_in[4];
    const float* patch_b= (const float*)d_in[5];
    const float* bn_g   = (const float*)d_in[6];
    const float* bn_b   = (const float*)d_in[7];
    const float* bn_m   = (const float*)d_in[8];
    const float* bn_v   = (const float*)d_in[9];
    const float* xpw    = (const float*)d_in[10];
    const float* dtw    = (const float*)d_in[11];
    const float* dtb    = (const float*)d_in[12];
    const float* alog   = (const float*)d_in[13];
    const float* Dsv    = (const float*)d_in[14];
    const float* lng    = (const float*)d_in[15];
    const float* lnb    = (const float*)d_in[16];
    const float* wo     = (const float*)d_in[17];
    float* out = (float*)d_out;

    float *xc, *xt, *dtrg, *bcv, *ysum, *hz, *pr, *hin;
    cudaGetSymbolAddress((void**)&xc,   g_xconv);
    cudaGetSymbolAddress((void**)&xt,   g_xt);
    cudaGetSymbolAddress((void**)&dtrg, g_dtr);
    cudaGetSymbolAddress((void**)&bcv,  g_bc);
    cudaGetSymbolAddress((void**)&ysum, g_ysum);
    cudaGetSymbolAddress((void**)&hz,   g_hz);
    cudaGetSymbolAddress((void**)&pr,   g_pr);
    cudaGetSymbolAddress((void**)&hin,  g_hin);

    cudaFuncSetAttribute(k_proj, cudaFuncAttributeMaxDynamicSharedMemorySize,
                         PROJ_SMEM);

    cudaMemsetAsync(ysum, 0, (size_t)BATCH * L * D * sizeof(float));

    dim3 blk64_8(64, 8);
    k_dwconv<<<BATCH * 4, 256>>>(x_in, conv_w, conv_b, xc);
    k_patch<<<dim3(4, BATCH), blk64_8>>>(xc, patch_w, patch_b,
                                         bn_g, bn_b, bn_m, bn_v, xt);
    k_proj<<<dim3(8, BATCH), 256, PROJ_SMEM>>>(xt, xpw, dtrg, bcv);
    k_scan1<<<dim3(12, BATCH), 64>>>(xt, dtrg, bcv, dtw, alog, dtb, hz, pr);
    k_comb<<<dim3(4, BATCH), 64>>>(hz, pr, hin);
    k_scan2<<<dim3(16, BATCH), 64>>>(xt, dtrg, bcv, dtw, alog, dtb, Dsv, hin, ysum);
    k_final<<<dim3(2, BATCH), 128>>>(x_in, ysum, ipw, lng, lnb, wo, out);
}

// round 12
// speedup vs baseline: 1.0883x; 1.0883x over previous
#include <cuda_runtime.h>
#include <cuda_bf16.h>

#define BATCH 256
#define L 256
#define D 64
#define NST 24
#define CPROJ 72   // DT_RANK + 2*NST

typedef unsigned long long u64;

// ---------------- scratch ----------------------------------------------------
__device__ float g_xconv[BATCH * 4 * 64 * 64];  // (b,c,h,w)
__device__ float g_xt[BATCH * L * D];           // (b,l,d)
__device__ float g_dtr[BATCH * 4 * NST * L];    // (b,k,r,l)
__device__ float g_bc[BATCH * 4 * 48 * L];      // (b,k,j,l)  j:0..23=B, 24..47=C
__device__ float g_ysum[BATCH * L * D];         // combined y (b,l,d)

__device__ __forceinline__ int map_l(int k, int l) {
    int lm = (k & 2) ? (255 - l) : l;
    if (k & 1) lm = ((lm & 15) << 4) | (lm >> 4);
    return lm;
}
__device__ __forceinline__ float silu(float x) { return x / (1.f + __expf(-x)); }

__device__ __forceinline__ u64 pk2(float lo, float hi) {
    u64 r; asm("mov.b64 %0,{%1,%2};" : "=l"(r) : "f"(lo), "f"(hi)); return r;
}
__device__ __forceinline__ void unpk2(float& lo, float& hi, u64 v) {
    asm("mov.b64 {%0,%1},%2;" : "=f"(lo), "=f"(hi) : "l"(v));
}
__device__ __forceinline__ u64 mul2(u64 a, u64 b) {
    u64 r; asm("mul.rn.f32x2 %0,%1,%2;" : "=l"(r) : "l"(a), "l"(b)); return r;
}
__device__ __forceinline__ u64 fma2(u64 a, u64 b, u64 c) {
    u64 r; asm("fma.rn.f32x2 %0,%1,%2,%3;" : "=l"(r) : "l"(a), "l"(b), "l"(c)); return r;
}
__device__ __forceinline__ unsigned f2tf(float f) {
    unsigned u; asm("cvt.rna.tf32.f32 %0,%1;" : "=r"(u) : "f"(f)); return u;
}
__device__ __forceinline__ void mma_tf32(float c[4],
                                         unsigned a0, unsigned a1, unsigned a2, unsigned a3,
                                         unsigned b0, unsigned b1) {
    asm volatile(
        "mma.sync.aligned.m16n8k8.row.col.f32.tf32.tf32.f32 "
        "{%0,%1,%2,%3},{%4,%5,%6,%7},{%8,%9},{%0,%1,%2,%3};"
        : "+f"(c[0]), "+f"(c[1]), "+f"(c[2]), "+f"(c[3])
        : "r"(a0), "r"(a1), "r"(a2), "r"(a3), "r"(b0), "r"(b1));
}

// ---------------- K2a: depthwise conv ----------------------------------------
__global__ void __launch_bounds__(256) k_dwconv(const float* __restrict__ xin,
                                                const float* __restrict__ cw,
                                                const float* __restrict__ cb,
                                                float* __restrict__ xc) {
    __shared__ float ts[66][68];
    int bc_ = blockIdx.x;
    int c = bc_ & 3, b = bc_ >> 2;
    int t = threadIdx.x;
    for (int i = t; i < 66 * 68; i += 256) ((float*)ts)[i] = 0.f;
    __syncthreads();
    const float* xb = xin + b * 16 * 16 * 64 + c * 16;
#pragma unroll
    for (int it = 0; it < 16; it++) {
        int e = it * 256 + t;
        int pq = e >> 4, ij = e & 15;
        int p = pq >> 4, q = pq & 15;
        int i2 = ij >> 2, j2 = ij & 3;
        ts[1 + p * 4 + i2][1 + q * 4 + j2] = xb[pq * 64 + ij];
    }
    __syncthreads();
    float wr[9];
#pragma unroll
    for (int i = 0; i < 9; i++) wr[i] = __ldg(&cw[c * 9 + i]);
    float cbv = __ldg(&cb[c]);
    int h = t >> 2, wq = t & 3;
    float* op = xc + (bc_ * 64 + h) * 64 + wq * 16;
#pragma unroll
    for (int j = 0; j < 16; j++) {
        int wcol = wq * 16 + j;
        float acc = cbv;
#pragma unroll
        for (int di = 0; di < 3; di++)
#pragma unroll
            for (int dj = 0; dj < 3; dj++)
                acc += ts[h + di][wcol + dj] * wr[di * 3 + dj];
        op[j] = silu(acc);
    }
}

// ---------------- K2b: patch conv + BN ---------------------------------------
__global__ void __launch_bounds__(512) k_patch(const float* __restrict__ xc,
                                               const float* __restrict__ pw,
                                               const float* __restrict__ pb,
                                               const float* __restrict__ gam,
                                               const float* __restrict__ bet,
                                               const float* __restrict__ mn,
                                               const float* __restrict__ vr,
                                               float* __restrict__ xt) {
    __shared__ __align__(16) float ws[64 * 65];
    __shared__ __align__(16) float px[64][64];
    int b = blockIdx.y, lg = blockIdx.x;
    int e = threadIdx.x, li = threadIdx.y;
    int t = li * 64 + e;
    for (int i = t; i < 4096; i += 512) ws[(i & 63) * 65 + (i >> 6)] = pw[i];
    for (int i = t; i < 4096; i += 512) {
        int row = i >> 6, m = i & 63;
        int l = lg * 64 + row;
        int ph = l >> 4, pwd = l & 15;
        int c = m >> 4, ij = m & 15, i2 = ij >> 2, j2 = ij & 3;
        px[row][m] = xc[((b * 4 + c) * 64 + ph * 4 + i2) * 64 + pwd * 4 + j2];
    }
    __syncthreads();
    float acc[8];
#pragma unroll
    for (int j = 0; j < 8; j++) acc[j] = 0.f;
    int r0 = li * 8;
#pragma unroll
    for (int m4 = 0; m4 < 16; m4++) {
        float4 xv[8];
#pragma unroll
        for (int j = 0; j < 8; j++) xv[j] = ((const float4*)px[r0 + j])[m4];
#pragma unroll
        for (int dd = 0; dd < 4; dd++) {
            float wv = ws[(m4 * 4 + dd) * 65 + e];
#pragma unroll
            for (int j = 0; j < 8; j++) {
                float v = dd == 0 ? xv[j].x : dd == 1 ? xv[j].y : dd == 2 ? xv[j].z : xv[j].w;
                acc[j] += v * wv;
            }
        }
    }
    float sc = __ldg(&gam[e]) * rsqrtf(__ldg(&vr[e]) + 1e-5f);
    float pbv = __ldg(&pb[e]), mnv = __ldg(&mn[e]), btv = __ldg(&bet[e]);
#pragma unroll
    for (int j = 0; j < 8; j++)
        xt[(b * 256 + lg * 64 + r0 + j) * 64 + e] = (acc[j] + pbv - mnv) * sc + btv;
}

// ---------------- K3: x_dbl projection via tf32 mma (R8 form) -----------------
#define AS_STRIDE 264
#define BS_STRIDE 72
__global__ void __launch_bounds__(256, 2) k_proj(const float* __restrict__ xt,
                                                 const float* __restrict__ xpw,
                                                 float* __restrict__ dtrg,
                                                 float* __restrict__ bc) {
    extern __shared__ unsigned sm[];
    unsigned* As = sm;
    unsigned* Bs = sm + 64 * AS_STRIDE;
    int k = blockIdx.x, b = blockIdx.y;
    int t = threadIdx.x, w = t >> 5, lane = t & 31;
    int gid = lane >> 2, tig = lane & 3;
    const float* wk = xpw + k * CPROJ * 64;

    for (int i = t; i < CPROJ * 64; i += 256) {
        int c = i >> 6, kk = i & 63;
        Bs[kk * BS_STRIDE + c] = f2tf(wk[i]);
    }
    {
        int lm = map_l(k, t);
        const float4* xp = (const float4*)(xt + (b * 256 + lm) * 64);
#pragma unroll
        for (int j4 = 0; j4 < 16; j4++) {
            float4 v = __ldg(xp + j4);
            As[(4 * j4 + 0) * AS_STRIDE + t] = f2tf(v.x);
            As[(4 * j4 + 1) * AS_STRIDE + t] = f2tf(v.y);
            As[(4 * j4 + 2) * AS_STRIDE + t] = f2tf(v.z);
            As[(4 * j4 + 3) * AS_STRIDE + t] = f2tf(v.w);
        }
    }
    __syncthreads();

    int r0 = w * 32;
    unsigned a[8][2][4];
#pragma unroll
    for (int ks = 0; ks < 8; ks++) {
        int kb = ks * 8;
#pragma unroll
        for (int mi = 0; mi < 2; mi++) {
            int r = r0 + mi * 16;
            a[ks][mi][0] = As[(kb + tig) * AS_STRIDE + r + gid];
            a[ks][mi][1] = As[(kb + tig) * AS_STRIDE + r + gid + 8];
            a[ks][mi][2] = As[(kb + tig + 4) * AS_STRIDE + r + gid];
            a[ks][mi][3] = As[(kb + tig + 4) * AS_STRIDE + r + gid + 8];
        }
    }

    float* dto = dtrg + (b * 4 + k) * NST * 256;
    float* bco = bc + (b * 4 + k) * 48 * 256;
#pragma unroll
    for (int n = 0; n < 9; n++) {
        float acc0[4] = {0.f, 0.f, 0.f, 0.f};
        float acc1[4] = {0.f, 0.f, 0.f, 0.f};
#pragma unroll
        for (int ks = 0; ks < 8; ks++) {
            int kb = ks * 8;
            unsigned b0 = Bs[(kb + tig) * BS_STRIDE + n * 8 + gid];
            unsigned b1 = Bs[(kb + tig + 4) * BS_STRIDE + n * 8 + gid];
            mma_tf32(acc0, a[ks][0][0], a[ks][0][1], a[ks][0][2], a[ks][0][3], b0, b1);
            mma_tf32(acc1, a[ks][1][0], a[ks][1][1], a[ks][1][2], a[ks][1][3], b0, b1);
        }
        int c0 = n * 8 + 2 * tig;
#pragma unroll
        for (int q = 0; q < 2; q++) {
            int c = c0 + q;
            float* base = (c < 24) ? (dto + c * 256) : (bco + (c - 24) * 256);
            base[r0 + gid]          = acc0[q];
            base[r0 + gid + 8]      = acc0[q + 2];
            base[r0 + 16 + gid]     = acc1[q];
            base[r0 + 16 + gid + 8] = acc1[q + 2];
        }
    }
}
#define PROJ_SMEM ((64 * AS_STRIDE + 64 * BS_STRIDE) * 4)

// ---------------- K4: scan, state-split across 2 CTAs -------------------------
// grid (8, B): k = bid.x & 3, g = bid.x >> 2 (state half). block 64 (thread/d).
// CTA g handles states [g*12, g*12+12); y combined via atomicAdd into ysum.
__global__ void __launch_bounds__(64, 10) k_scan(const float* __restrict__ xt,
                                                 const float* __restrict__ dtrg,
                                                 const float* __restrict__ bc,
                                                 const float* __restrict__ dtw_g,
                                                 const float* __restrict__ alog,
                                                 const float* __restrict__ dbias,
                                                 const float* __restrict__ Dsv,
                                                 float* __restrict__ ysum) {
    __shared__ __align__(16) float sbc[16][24];   // [i][0..11]=B half, [12..23]=C half
    __shared__ __align__(16) float sdtr[NST * 16];
    __shared__ float su[16][64];
    __shared__ float sdtw[NST * 64];              // [r][d]
    int kg = blockIdx.x, b = blockIdx.y;
    int k = kg & 3, g = kg >> 2;
    int nbase = g * 12;
    int d = threadIdx.x;
    int kd = k * 64 + d;

    {   // stage dt weights
        const float4* dwp = (const float4*)(dtw_g + kd * NST);
#pragma unroll
        for (int i = 0; i < 6; i++) {
            float4 v = __ldg(dwp + i);
            sdtw[(4 * i + 0) * 64 + d] = v.x;
            sdtw[(4 * i + 1) * 64 + d] = v.y;
            sdtw[(4 * i + 2) * 64 + d] = v.z;
            sdtw[(4 * i + 3) * 64 + d] = v.w;
        }
    }
    float a0 = -__expf(__ldg(&alog[kd * NST]));
    bool chain = (a0 != 0.f);
#pragma unroll
    for (int n = 1; n < NST; n++) {
        float an = -__expf(__ldg(&alog[kd * NST + n]));
        chain = chain && (fabsf(an - (float)(n + 1) * a0) <= 1e-4f * fabsf(an));
    }
    float bias = __ldg(&dbias[kd]);
    // D*u term: only half g==0 adds it (avoid double count)
    float Dv = (g == 0) ? __ldg(&Dsv[kd]) : 0.f;
    int kb = b * 4 + k;
    const float* dtrp = dtrg + kb * NST * 256;
    const float* bcp = bc + kb * 48 * 256;
    const float* xrow = xt + b * 256 * 64;
    float* yb = ysum + b * 256 * 64;

    u64 h2[6];
#pragma unroll
    for (int p = 0; p < 6; p++) h2[p] = 0ull;

    int chainU = __syncthreads_and(chain ? 1 : 0);

    for (int l0 = 0; l0 < 256; l0 += 16) {
        __syncthreads();
#pragma unroll
        for (int m = 0; m < 6; m++) {
            int idx = d * 6 + m;
            int i = idx & 15, jj = idx >> 4;   // jj 0..23
            int j = (jj < 12) ? (nbase + jj) : (24 + nbase + (jj - 12));
            sbc[i][jj] = bcp[j * 256 + l0 + i];
        }
#pragma unroll
        for (int m = 0; m < 6; m++) {
            int idx = d * 6 + m;
            sdtr[idx] = dtrp[(idx >> 4) * 256 + l0 + (idx & 15)];
        }
#pragma unroll
        for (int i = 0; i < 16; i++)
            su[i][d] = __ldg(&xrow[map_l(k, l0 + i) * 64 + d]);
        __syncthreads();

        float dtc[16];
        {
            u64 dt2[8];
#pragma unroll
            for (int ip = 0; ip < 8; ip++) dt2[ip] = 0ull;
#pragma unroll
            for (int r = 0; r < NST; r++) {
                float wv = sdtw[r * 64 + d];
                u64 wp = pk2(wv, wv);
#pragma unroll
                for (int q = 0; q < 4; q++) {
                    ulonglong2 v = *(const ulonglong2*)&sdtr[r * 16 + 4 * q];
                    dt2[2 * q]     = fma2(wp, v.x, dt2[2 * q]);
                    dt2[2 * q + 1] = fma2(wp, v.y, dt2[2 * q + 1]);
                }
            }
#pragma unroll
            for (int ip = 0; ip < 8; ip++) unpk2(dtc[2 * ip], dtc[2 * ip + 1], dt2[ip]);
        }

        if (chainU) {
#pragma unroll 2
            for (int i = 0; i < 16; i++) {
                int l = l0 + i;
                float xv = dtc[i] + bias;
                float delta = (xv > 15.f) ? xv : __logf(1.f + __expf(xv));
                float u = su[i][d];
                float du = delta * u;
                float q = __expf(delta * a0);
                float q2s = q * q;
                u64 qq = pk2(q2s, q2s);
                u64 dA;
                if (g == 0) {
                    dA = pk2(q, q2s);
                } else {
                    float q4s = q2s * q2s, q8s = q4s * q4s, q12s = q8s * q4s;
                    dA = pk2(q12s * q, q12s * q2s);   // q^13, q^14
                }
                u64 du2 = pk2(du, du);
                u64 y2a = 0ull, y2b = 0ull;
#pragma unroll
                for (int p = 0; p < 6; p++) {
                    u64 B2 = *(const u64*)&sbc[i][2 * p];
                    u64 C2 = *(const u64*)&sbc[i][12 + 2 * p];
                    h2[p] = fma2(dA, h2[p], mul2(du2, B2));
                    if (p & 1) y2b = fma2(h2[p], C2, y2b);
                    else       y2a = fma2(h2[p], C2, y2a);
                    if (p < 5) dA = mul2(dA, qq);
                }
                float ylo, yhi, zlo, zhi;
                unpk2(ylo, yhi, y2a); unpk2(zlo, zhi, y2b);
                atomicAdd(&yb[map_l(k, l) * 64 + d], ylo + yhi + zlo + zhi + Dv * u);
            }
        } else {
#pragma unroll 1
            for (int i = 0; i < 16; i++) {
                int l = l0 + i;
                float xv = dtc[i] + bias;
                float delta = (xv > 15.f) ? xv : __logf(1.f + __expf(xv));
                float u = su[i][d];
                float du = delta * u;
                u64 du2 = pk2(du, du);
                u64 y2 = 0ull;
#pragma unroll
                for (int p = 0; p < 6; p++) {
                    float alo = -__expf(__ldg(&alog[kd * NST + nbase + 2 * p]));
                    float ahi = -__expf(__ldg(&alog[kd * NST + nbase + 2 * p + 1]));
                    u64 dA = pk2(__expf(delta * alo), __expf(delta * ahi));
                    u64 B2 = *(const u64*)&sbc[i][2 * p];
                    u64 C2 = *(const u64*)&sbc[i][12 + 2 * p];
                    h2[p] = fma2(dA, h2[p], mul2(du2, B2));
                    y2 = fma2(h2[p], C2, y2);
                }
                float ylo, yhi;
                unpk2(ylo, yhi, y2);
                atomicAdd(&yb[map_l(k, l) * 64 + d], ylo + yhi + Dv * u);
            }
        }
    }
}

// ---------------- K5: LN + inline z-gate + out_proj (R8 form) -----------------
__global__ void __launch_bounds__(256) k_final(const float* __restrict__ xin,
                                               const float* __restrict__ ysum,
                                               const float* __restrict__ ipw,
                                               const float* __restrict__ lng,
                                               const float* __restrict__ lnb,
                                               const float* __restrict__ wo,
                                               float* __restrict__ out) {
    __shared__ __align__(16) float wsI[64 * 64];
    __shared__ __align__(16) float wsO[64 * 64];
    __shared__ float gs[64], bs[64];
    int b = blockIdx.x, l = threadIdx.x;
    for (int i = l; i < 4096; i += 256) { wsI[i] = ipw[i]; wsO[i] = wo[i]; }
    if (l < 64) { gs[l] = lng[l]; bs[l] = lnb[l]; }
    __syncthreads();

    float yv[64];
    u64 xr2[32];
    float mu = 0.f;
    {
        const float4* yp = (const float4*)(ysum + (b * 256 + l) * 64);
        const float4* xp = (const float4*)(xin + (b * 256 + l) * 64);
#pragma unroll
        for (int i = 0; i < 16; i++) {
            float4 v = yp[i];
            yv[4 * i + 0] = v.x; yv[4 * i + 1] = v.y;
            yv[4 * i + 2] = v.z; yv[4 * i + 3] = v.w;
            mu += v.x + v.y + v.z + v.w;
            float4 x = xp[i];
            xr2[2 * i]     = pk2(x.x, x.y);
            xr2[2 * i + 1] = pk2(x.z, x.w);
        }
    }
    mu *= (1.f / 64.f);
    float var = 0.f;
#pragma unroll
    for (int e = 0; e < 64; e++) { float tv = yv[e] - mu; var += tv * tv; }
    var *= (1.f / 64.f);
    float rs = rsqrtf(var + 1e-5f);

    u64 g2[32];
#pragma unroll
    for (int e2 = 0; e2 < 32; e2++) {
        float ge[2];
#pragma unroll
        for (int hh = 0; hh < 2; hh++) {
            int e = 2 * e2 + hh;
            const u64* wrow = (const u64*)&wsI[e * 64];
            u64 acc = 0ull;
#pragma unroll
            for (int j = 0; j < 32; j++) acc = fma2(xr2[j], wrow[j], acc);
            float lo, hi; unpk2(lo, hi, acc);
            float zv = silu(lo + hi);
            ge[hh] = ((yv[e] - mu) * rs * gs[e] + bs[e]) * zv;
        }
        g2[e2] = pk2(ge[0], ge[1]);
    }

    float4* op = (float4*)(out + (b * 256 + l) * 64);
#pragma unroll 1
    for (int dg = 0; dg < 16; dg++) {
        float res[4];
#pragma unroll
        for (int q = 0; q < 4; q++) {
            const u64* wrow = (const u64*)&wsO[(dg * 4 + q) * 64];
            u64 acc = 0ull;
#pragma unroll
            for (int j = 0; j < 32; j++) acc = fma2(g2[j], wrow[j], acc);
            float lo, hi; unpk2(lo, hi, acc);
            res[q] = lo + hi;
        }
        op[dg] = make_float4(res[0], res[1], res[2], res[3]);
    }
}

// ---------------- launch ------------------------------------------------------
extern "C" void kernel_launch(void* const* d_in, const int* in_sizes, int n_in,
                              void* d_out, int out_size) {
    const float* x_in   = (const float*)d_in[0];
    const float* ipw    = (const float*)d_in[1];
    const float* conv_w = (const float*)d_in[2];
    const float* conv_b = (const float*)d_in[3];
    const float* patch_w= (const float*)d_in[4];
    const float* patch_b= (const float*)d_in[5];
    const float* bn_g   = (const float*)d_in[6];
    const float* bn_b   = (const float*)d_in[7];
    const float* bn_m   = (const float*)d_in[8];
    const float* bn_v   = (const float*)d_in[9];
    const float* xpw    = (const float*)d_in[10];
    const float* dtw    = (const float*)d_in[11];
    const float* dtb    = (const float*)d_in[12];
    const float* alog   = (const float*)d_in[13];
    const float* Dsv    = (const float*)d_in[14];
    const float* lng    = (const float*)d_in[15];
    const float* lnb    = (const float*)d_in[16];
    const float* wo     = (const float*)d_in[17];
    float* out = (float*)d_out;

    float *xc, *xt, *dtrg, *bcv, *ysum;
    cudaGetSymbolAddress((void**)&xc,   g_xconv);
    cudaGetSymbolAddress((void**)&xt,   g_xt);
    cudaGetSymbolAddress((void**)&dtrg, g_dtr);
    cudaGetSymbolAddress((void**)&bcv,  g_bc);
    cudaGetSymbolAddress((void**)&ysum, g_ysum);

    cudaFuncSetAttribute(k_proj, cudaFuncAttributeMaxDynamicSharedMemorySize,
                         PROJ_SMEM);

    cudaMemsetAsync(ysum, 0, (size_t)BATCH * L * D * sizeof(float));

    dim3 blk64_8(64, 8);
    k_dwconv<<<BATCH * 4, 256>>>(x_in, conv_w, conv_b, xc);
    k_patch<<<dim3(4, BATCH), blk64_8>>>(xc, patch_w, patch_b,
                                         bn_g, bn_b, bn_m, bn_v, xt);
    k_proj<<<dim3(4, BATCH), 256, PROJ_SMEM>>>(xt, xpw, dtrg, bcv);
    k_scan<<<dim3(8, BATCH), 64>>>(xt, dtrg, bcv, dtw, alog, dtb, Dsv, ysum);
    k_final<<<BATCH, 256>>>(x_in, ysum, ipw, lng, lnb, wo, out);
}

// round 13
// speedup vs baseline: 1.3116x; 1.2052x over previous
#include <cuda_runtime.h>
#include <cuda_bf16.h>

#define BATCH 256
#define L 256
#define D 64
#define NST 24
#define CPROJ 72   // DT_RANK + 2*NST

typedef unsigned long long u64;

// ---------------- scratch ----------------------------------------------------
__device__ float g_xt[BATCH * L * D];           // (b,l,d)
__device__ float g_dtr[BATCH * 4 * NST * L];    // (b,k,r,l)
__device__ float g_bc[BATCH * 4 * 48 * L];      // (b,k,j,l)  j:0..23=B, 24..47=C
__device__ float g_ysum[BATCH * L * D];         // combined y (b,l,d)

__device__ __forceinline__ int map_l(int k, int l) {
    int lm = (k & 2) ? (255 - l) : l;
    if (k & 1) lm = ((lm & 15) << 4) | (lm >> 4);
    return lm;
}
__device__ __forceinline__ float silu(float x) { return x / (1.f + __expf(-x)); }

__device__ __forceinline__ u64 pk2(float lo, float hi) {
    u64 r; asm("mov.b64 %0,{%1,%2};" : "=l"(r) : "f"(lo), "f"(hi)); return r;
}
__device__ __forceinline__ void unpk2(float& lo, float& hi, u64 v) {
    asm("mov.b64 {%0,%1},%2;" : "=f"(lo), "=f"(hi) : "l"(v));
}
__device__ __forceinline__ u64 mul2(u64 a, u64 b) {
    u64 r; asm("mul.rn.f32x2 %0,%1,%2;" : "=l"(r) : "l"(a), "l"(b)); return r;
}
__device__ __forceinline__ u64 fma2(u64 a, u64 b, u64 c) {
    u64 r; asm("fma.rn.f32x2 %0,%1,%2,%3;" : "=l"(r) : "l"(a), "l"(b), "l"(c)); return r;
}
__device__ __forceinline__ unsigned f2tf(float f) {
    unsigned u; asm("cvt.rna.tf32.f32 %0,%1;" : "=r"(u) : "f"(f)); return u;
}
__device__ __forceinline__ void mma_tf32(float c[4],
                                         unsigned a0, unsigned a1, unsigned a2, unsigned a3,
                                         unsigned b0, unsigned b1) {
    asm volatile(
        "mma.sync.aligned.m16n8k8.row.col.f32.tf32.tf32.f32 "
        "{%0,%1,%2,%3},{%4,%5,%6,%7},{%8,%9},{%0,%1,%2,%3};"
        : "+f"(c[0]), "+f"(c[1]), "+f"(c[2]), "+f"(c[3])
        : "r"(a0), "r"(a1), "r"(a2), "r"(a3), "r"(b0), "r"(b1));
}

// ---------------- K1: fused rearrange + dwconv + silu + patch + BN ------------
// grid (B), block 512. smem: ws[64*65] | xcs[4*64*68] | ts[66*68]
#define FRONT_SMEM ((64 * 65 + 4 * 64 * 68 + 66 * 68) * 4)
__global__ void __launch_bounds__(512) k_front(const float* __restrict__ xin,
                                               const float* __restrict__ cw,
                                               const float* __restrict__ cb,
                                               const float* __restrict__ pw,
                                               const float* __restrict__ pb,
                                               const float* __restrict__ gam,
                                               const float* __restrict__ bet,
                                               const float* __restrict__ mn,
                                               const float* __restrict__ vr,
                                               float* __restrict__ xt,
                                               float* __restrict__ ysum) {
    extern __shared__ float fsm[];
    float* ws  = fsm;                     // [m*65+e] = pw[e*64+m]
    float* xcs = fsm + 64 * 65;           // [c][64][68]
    float* ts  = xcs + 4 * 64 * 68;       // [66][68] halo, reused per c
    int b = blockIdx.x;
    int t = threadIdx.x;

    // zero ysum slice for this b (consumed by k_scan's atomics later)
    {
        float4* yz = (float4*)(ysum + b * 16384);
        float4 z4 = make_float4(0.f, 0.f, 0.f, 0.f);
#pragma unroll
        for (int i = 0; i < 8; i++) yz[t + i * 512] = z4;
    }
    // stage patch weights transposed
    for (int i = t; i < 4096; i += 512) ws[(i & 63) * 65 + (i >> 6)] = pw[i];

    const float* xbb = xin + b * 16384;
#pragma unroll 1
    for (int c = 0; c < 4; c++) {
        __syncthreads();
        for (int i = t; i < 66 * 68; i += 512) ts[i] = 0.f;
        __syncthreads();
        const float* xb = xbb + c * 16;
#pragma unroll
        for (int it = 0; it < 8; it++) {
            int e = it * 512 + t;
            int pq = e >> 4, ij = e & 15;
            int p = pq >> 4, q = pq & 15;
            int i2 = ij >> 2, j2 = ij & 3;
            ts[(1 + p * 4 + i2) * 68 + 1 + q * 4 + j2] = xb[pq * 64 + ij];
        }
        __syncthreads();
        float wr[9];
#pragma unroll
        for (int i = 0; i < 9; i++) wr[i] = __ldg(&cw[c * 9 + i]);
        float cbv = __ldg(&cb[c]);
        int h = t >> 3, wq = t & 7;
        float* orow = xcs + (c * 64 + h) * 68;
#pragma unroll
        for (int j = 0; j < 8; j++) {
            int wcol = wq * 8 + j;
            float acc = cbv;
#pragma unroll
            for (int di = 0; di < 3; di++)
#pragma unroll
                for (int dj = 0; dj < 3; dj++)
                    acc += ts[(h + di) * 68 + wcol + dj] * wr[di * 3 + dj];
            orow[wcol] = silu(acc);
        }
    }
    __syncthreads();

    // patch GEMM + BN: e = output channel, li*8+j = row within group
    int e = t & 63, li = t >> 6;   // li 0..7
    float sc = __ldg(&gam[e]) * rsqrtf(__ldg(&vr[e]) + 1e-5f);
    float pbv = __ldg(&pb[e]), mnv = __ldg(&mn[e]), btv = __ldg(&bet[e]);
#pragma unroll 1
    for (int rg = 0; rg < 4; rg++) {
        int r0 = rg * 64 + li * 8;
        int rof[8];
#pragma unroll
        for (int j = 0; j < 8; j++) {
            int row = r0 + j;
            rof[j] = ((row >> 4) * 4) * 68 + (row & 15) * 4;
        }
        float acc[8];
#pragma unroll
        for (int j = 0; j < 8; j++) acc[j] = 0.f;
#pragma unroll
        for (int m4 = 0; m4 < 16; m4++) {
            int c4 = m4 >> 2, i2m = m4 & 3;
            int boff = c4 * 4352 + i2m * 68;   // 4352 = 64*68
            float4 xv[8];
#pragma unroll
            for (int j = 0; j < 8; j++)
                xv[j] = *(const float4*)&xcs[boff + rof[j]];
#pragma unroll
            for (int dd = 0; dd < 4; dd++) {
                float wv = ws[(m4 * 4 + dd) * 65 + e];
#pragma unroll
                for (int j = 0; j < 8; j++) {
                    float v = dd == 0 ? xv[j].x : dd == 1 ? xv[j].y : dd == 2 ? xv[j].z : xv[j].w;
                    acc[j] += v * wv;
                }
            }
        }
#pragma unroll
        for (int j = 0; j < 8; j++)
            xt[(b * 256 + r0 + j) * 64 + e] = (acc[j] + pbv - mnv) * sc + btv;
    }
}

// ---------------- K3: x_dbl projection via tf32 mma (R8 form) -----------------
#define AS_STRIDE 264
#define BS_STRIDE 72
__global__ void __launch_bounds__(256, 2) k_proj(const float* __restrict__ xt,
                                                 const float* __restrict__ xpw,
                                                 float* __restrict__ dtrg,
                                                 float* __restrict__ bc) {
    extern __shared__ unsigned sm[];
    unsigned* As = sm;
    unsigned* Bs = sm + 64 * AS_STRIDE;
    int k = blockIdx.x, b = blockIdx.y;
    int t = threadIdx.x, w = t >> 5, lane = t & 31;
    int gid = lane >> 2, tig = lane & 3;
    const float* wk = xpw + k * CPROJ * 64;

    for (int i = t; i < CPROJ * 64; i += 256) {
        int c = i >> 6, kk = i & 63;
        Bs[kk * BS_STRIDE + c] = f2tf(wk[i]);
    }
    {
        int lm = map_l(k, t);
        const float4* xp = (const float4*)(xt + (b * 256 + lm) * 64);
#pragma unroll
        for (int j4 = 0; j4 < 16; j4++) {
            float4 v = __ldg(xp + j4);
            As[(4 * j4 + 0) * AS_STRIDE + t] = f2tf(v.x);
            As[(4 * j4 + 1) * AS_STRIDE + t] = f2tf(v.y);
            As[(4 * j4 + 2) * AS_STRIDE + t] = f2tf(v.z);
            As[(4 * j4 + 3) * AS_STRIDE + t] = f2tf(v.w);
        }
    }
    __syncthreads();

    int r0 = w * 32;
    unsigned a[8][2][4];
#pragma unroll
    for (int ks = 0; ks < 8; ks++) {
        int kb = ks * 8;
#pragma unroll
        for (int mi = 0; mi < 2; mi++) {
            int r = r0 + mi * 16;
            a[ks][mi][0] = As[(kb + tig) * AS_STRIDE + r + gid];
            a[ks][mi][1] = As[(kb + tig) * AS_STRIDE + r + gid + 8];
            a[ks][mi][2] = As[(kb + tig + 4) * AS_STRIDE + r + gid];
            a[ks][mi][3] = As[(kb + tig + 4) * AS_STRIDE + r + gid + 8];
        }
    }

    float* dto = dtrg + (b * 4 + k) * NST * 256;
    float* bco = bc + (b * 4 + k) * 48 * 256;
#pragma unroll
    for (int n = 0; n < 9; n++) {
        float acc0[4] = {0.f, 0.f, 0.f, 0.f};
        float acc1[4] = {0.f, 0.f, 0.f, 0.f};
#pragma unroll
        for (int ks = 0; ks < 8; ks++) {
            int kb = ks * 8;
            unsigned b0 = Bs[(kb + tig) * BS_STRIDE + n * 8 + gid];
            unsigned b1 = Bs[(kb + tig + 4) * BS_STRIDE + n * 8 + gid];
            mma_tf32(acc0, a[ks][0][0], a[ks][0][1], a[ks][0][2], a[ks][0][3], b0, b1);
            mma_tf32(acc1, a[ks][1][0], a[ks][1][1], a[ks][1][2], a[ks][1][3], b0, b1);
        }
        int c0 = n * 8 + 2 * tig;
#pragma unroll
        for (int q = 0; q < 2; q++) {
            int c = c0 + q;
            float* base = (c < 24) ? (dto + c * 256) : (bco + (c - 24) * 256);
            base[r0 + gid]          = acc0[q];
            base[r0 + gid + 8]      = acc0[q + 2];
            base[r0 + 16 + gid]     = acc1[q];
            base[r0 + 16 + gid + 8] = acc1[q + 2];
        }
    }
}
#define PROJ_SMEM ((64 * AS_STRIDE + 64 * BS_STRIDE) * 4)

// ---------------- K4: scan (R8 form, unchanged) -------------------------------
__global__ void __launch_bounds__(64) k_scan(const float* __restrict__ xt,
                                             const float* __restrict__ dtrg,
                                             const float* __restrict__ bc,
                                             const float* __restrict__ dtw_g,
                                             const float* __restrict__ alog,
                                             const float* __restrict__ dbias,
                                             const float* __restrict__ Dsv,
                                             float* __restrict__ ysum) {
    __shared__ __align__(16) float sbc[16][48];
    __shared__ __align__(16) float sdtr[NST * 16];
    __shared__ float su[16][64];
    int k = blockIdx.x, b = blockIdx.y;
    int d = threadIdx.x;
    int kd = k * 64 + d;

    float dtw[NST];
    {
        const float4* dwp = (const float4*)(dtw_g + kd * NST);
#pragma unroll
        for (int i = 0; i < 6; i++) {
            float4 v = __ldg(dwp + i);
            dtw[4 * i] = v.x; dtw[4 * i + 1] = v.y;
            dtw[4 * i + 2] = v.z; dtw[4 * i + 3] = v.w;
        }
    }
    float a0 = -__expf(__ldg(&alog[kd * NST]));
    bool chain = (a0 != 0.f);
#pragma unroll
    for (int n = 1; n < NST; n++) {
        float an = -__expf(__ldg(&alog[kd * NST + n]));
        chain = chain && (fabsf(an - (float)(n + 1) * a0) <= 1e-4f * fabsf(an));
    }
    float bias = __ldg(&dbias[kd]);
    float Dv = __ldg(&Dsv[kd]);
    int kb = b * 4 + k;
    const float* dtrp = dtrg + kb * NST * 256;
    const float* bcp = bc + kb * 48 * 256;
    const float* xrow = xt + b * 256 * 64;
    float* yb = ysum + b * 256 * 64;

    u64 h2[12];
#pragma unroll
    for (int p = 0; p < 12; p++) h2[p] = 0ull;

    for (int l0 = 0; l0 < 256; l0 += 16) {
        __syncthreads();
#pragma unroll
        for (int m = 0; m < 12; m++) {
            int idx = d * 12 + m;
            sbc[idx & 15][idx >> 4] = bcp[(idx >> 4) * 256 + l0 + (idx & 15)];
        }
#pragma unroll
        for (int m = 0; m < 6; m++) {
            int idx = d * 6 + m;
            sdtr[idx] = dtrp[(idx >> 4) * 256 + l0 + (idx & 15)];
        }
#pragma unroll
        for (int i = 0; i < 16; i++)
            su[i][d] = __ldg(&xrow[map_l(k, l0 + i) * 64 + d]);
        __syncthreads();

        float dtc[16];
        {
            u64 dt2[8];
#pragma unroll
            for (int ip = 0; ip < 8; ip++) dt2[ip] = 0ull;
#pragma unroll
            for (int r = 0; r < NST; r++) {
                u64 wp = pk2(dtw[r], dtw[r]);
#pragma unroll
                for (int q = 0; q < 4; q++) {
                    ulonglong2 v = *(const ulonglong2*)&sdtr[r * 16 + 4 * q];
                    dt2[2 * q]     = fma2(wp, v.x, dt2[2 * q]);
                    dt2[2 * q + 1] = fma2(wp, v.y, dt2[2 * q + 1]);
                }
            }
#pragma unroll
            for (int ip = 0; ip < 8; ip++) unpk2(dtc[2 * ip], dtc[2 * ip + 1], dt2[ip]);
        }

        if (chain) {
#pragma unroll 2
            for (int i = 0; i < 16; i++) {
                int l = l0 + i;
                float xv = dtc[i] + bias;
                float delta = (xv > 15.f) ? xv : __logf(1.f + __expf(xv));
                float u = su[i][d];
                float du = delta * u;
                float q = __expf(delta * a0);
                float q2s = q * q, q4s = q2s * q2s, q8s = q4s * q4s, q16s = q8s * q8s;
                u64 Q2 = pk2(q2s, q2s), Q4 = pk2(q4s, q4s);
                u64 Q8 = pk2(q8s, q8s), Q16 = pk2(q16s, q16s);
                u64 P[12];
                P[0] = pk2(q, q2s);
                P[1] = mul2(P[0], Q2);
                P[2] = mul2(P[0], Q4);  P[3] = mul2(P[1], Q4);
                P[4] = mul2(P[0], Q8);  P[5] = mul2(P[1], Q8);
                P[6] = mul2(P[2], Q8);  P[7] = mul2(P[3], Q8);
                P[8] = mul2(P[0], Q16); P[9] = mul2(P[1], Q16);
                P[10] = mul2(P[2], Q16); P[11] = mul2(P[3], Q16);
                u64 du2 = pk2(du, du);
                u64 y2a = 0ull, y2b = 0ull;
#pragma unroll
                for (int qq = 0; qq < 6; qq++) {
                    ulonglong2 Bv = *(const ulonglong2*)&sbc[i][4 * qq];
                    ulonglong2 Cv = *(const ulonglong2*)&sbc[i][24 + 4 * qq];
                    int p0 = 2 * qq, p1 = 2 * qq + 1;
                    h2[p0] = fma2(P[p0], h2[p0], mul2(du2, Bv.x));
                    y2a = fma2(h2[p0], Cv.x, y2a);
                    h2[p1] = fma2(P[p1], h2[p1], mul2(du2, Bv.y));
                    y2b = fma2(h2[p1], Cv.y, y2b);
                }
                float ylo, yhi, zlo, zhi;
                unpk2(ylo, yhi, y2a); unpk2(zlo, zhi, y2b);
                atomicAdd(&yb[map_l(k, l) * 64 + d], ylo + yhi + zlo + zhi + Dv * u);
            }
        } else {
#pragma unroll 1
            for (int i = 0; i < 16; i++) {
                int l = l0 + i;
                float xv = dtc[i] + bias;
                float delta = (xv > 15.f) ? xv : __logf(1.f + __expf(xv));
                float u = su[i][d];
                float du = delta * u;
                u64 du2 = pk2(du, du);
                u64 y2 = 0ull;
#pragma unroll
                for (int qq = 0; qq < 6; qq++) {
                    ulonglong2 Bv = *(const ulonglong2*)&sbc[i][4 * qq];
                    ulonglong2 Cv = *(const ulonglong2*)&sbc[i][24 + 4 * qq];
#pragma unroll
                    for (int s = 0; s < 2; s++) {
                        int p = 2 * qq + s;
                        float alo = -__expf(__ldg(&alog[kd * NST + 2 * p]));
                        float ahi = -__expf(__ldg(&alog[kd * NST + 2 * p + 1]));
                        u64 dA = pk2(__expf(delta * alo), __expf(delta * ahi));
                        u64 Bp = s ? Bv.y : Bv.x;
                        u64 Cp = s ? Cv.y : Cv.x;
                        h2[p] = fma2(dA, h2[p], mul2(du2, Bp));
                        y2 = fma2(h2[p], Cp, y2);
                    }
                }
                float ylo, yhi;
                unpk2(ylo, yhi, y2);
                atomicAdd(&yb[map_l(k, l) * 64 + d], ylo + yhi + Dv * u);
            }
        }
    }
}

// ---------------- K5: LN + inline z-gate + out_proj (R8 form) -----------------
__global__ void __launch_bounds__(256) k_final(const float* __restrict__ xin,
                                               const float* __restrict__ ysum,
                                               const float* __restrict__ ipw,
                                               const float* __restrict__ lng,
                                               const float* __restrict__ lnb,
                                               const float* __restrict__ wo,
                                               float* __restrict__ out) {
    __shared__ __align__(16) float wsI[64 * 64];
    __shared__ __align__(16) float wsO[64 * 64];
    __shared__ float gs[64], bs[64];
    int b = blockIdx.x, l = threadIdx.x;
    for (int i = l; i < 4096; i += 256) { wsI[i] = ipw[i]; wsO[i] = wo[i]; }
    if (l < 64) { gs[l] = lng[l]; bs[l] = lnb[l]; }
    __syncthreads();

    float yv[64];
    u64 xr2[32];
    float mu = 0.f;
    {
        const float4* yp = (const float4*)(ysum + (b * 256 + l) * 64);
        const float4* xp = (const float4*)(xin + (b * 256 + l) * 64);
#pragma unroll
        for (int i = 0; i < 16; i++) {
            float4 v = yp[i];
            yv[4 * i + 0] = v.x; yv[4 * i + 1] = v.y;
            yv[4 * i + 2] = v.z; yv[4 * i + 3] = v.w;
            mu += v.x + v.y + v.z + v.w;
            float4 x = xp[i];
            xr2[2 * i]     = pk2(x.x, x.y);
            xr2[2 * i + 1] = pk2(x.z, x.w);
        }
    }
    mu *= (1.f / 64.f);
    float var = 0.f;
#pragma unroll
    for (int e = 0; e < 64; e++) { float tv = yv[e] - mu; var += tv * tv; }
    var *= (1.f / 64.f);
    float rs = rsqrtf(var + 1e-5f);

    u64 g2[32];
#pragma unroll
    for (int e2 = 0; e2 < 32; e2++) {
        float ge[2];
#pragma unroll
        for (int hh = 0; hh < 2; hh++) {
            int e = 2 * e2 + hh;
            const u64* wrow = (const u64*)&wsI[e * 64];
            u64 acc = 0ull;
#pragma unroll
            for (int j = 0; j < 32; j++) acc = fma2(xr2[j], wrow[j], acc);
            float lo, hi; unpk2(lo, hi, acc);
            float zv = silu(lo + hi);
            ge[hh] = ((yv[e] - mu) * rs * gs[e] + bs[e]) * zv;
        }
        g2[e2] = pk2(ge[0], ge[1]);
    }

    float4* op = (float4*)(out + (b * 256 + l) * 64);
#pragma unroll 1
    for (int dg = 0; dg < 16; dg++) {
        float res[4];
#pragma unroll
        for (int q = 0; q < 4; q++) {
            const u64* wrow = (const u64*)&wsO[(dg * 4 + q) * 64];
            u64 acc = 0ull;
#pragma unroll
            for (int j = 0; j < 32; j++) acc = fma2(g2[j], wrow[j], acc);
            float lo, hi; unpk2(lo, hi, acc);
            res[q] = lo + hi;
        }
        op[dg] = make_float4(res[0], res[1], res[2], res[3]);
    }
}

// ---------------- launch ------------------------------------------------------
extern "C" void kernel_launch(void* const* d_in, const int* in_sizes, int n_in,
                              void* d_out, int out_size) {
    const float* x_in   = (const float*)d_in[0];
    const float* ipw    = (const float*)d_in[1];
    const float* conv_w = (const float*)d_in[2];
    const float* conv_b = (const float*)d_in[3];
    const float* patch_w= (const float*)d_in[4];
    const float* patch_b= (const float*)d_in[5];
    const float* bn_g   = (const float*)d_in[6];
    const float* bn_b   = (const float*)d_in[7];
    const float* bn_m   = (const float*)d_in[8];
    const float* bn_v   = (const float*)d_in[9];
    const float* xpw    = (const float*)d_in[10];
    const float* dtw    = (const float*)d_in[11];
    const float* dtb    = (const float*)d_in[12];
    const float* alog   = (const float*)d_in[13];
    const float* Dsv    = (const float*)d_in[14];
    const float* lng    = (const float*)d_in[15];
    const float* lnb    = (const float*)d_in[16];
    const float* wo     = (const float*)d_in[17];
    float* out = (float*)d_out;

    float *xt, *dtrg, *bcv, *ysum;
    cudaGetSymbolAddress((void**)&xt,   g_xt);
    cudaGetSymbolAddress((void**)&dtrg, g_dtr);
    cudaGetSymbolAddress((void**)&bcv,  g_bc);
    cudaGetSymbolAddress((void**)&ysum, g_ysum);

    cudaFuncSetAttribute(k_front, cudaFuncAttributeMaxDynamicSharedMemorySize,
                         FRONT_SMEM);
    cudaFuncSetAttribute(k_proj, cudaFuncAttributeMaxDynamicSharedMemorySize,
                         PROJ_SMEM);

    k_front<<<BATCH, 512, FRONT_SMEM>>>(x_in, conv_w, conv_b, patch_w, patch_b,
                                        bn_g, bn_b, bn_m, bn_v, xt, ysum);
    k_proj<<<dim3(4, BATCH), 256, PROJ_SMEM>>>(xt, xpw, dtrg, bcv);
    k_scan<<<dim3(4, BATCH), 64>>>(xt, dtrg, bcv, dtw, alog, dtb, Dsv, ysum);
    k_final<<<BATCH, 256>>>(x_in, ysum, ipw, lng, lnb, wo, out);
}

// round 14
// speedup vs baseline: 1.4081x; 1.0735x over previous
#include <cuda_runtime.h>
#include <cuda_bf16.h>

#define BATCH 256
#define L 256
#define D 64
#define NST 24
#define CPROJ 72   // DT_RANK + 2*NST

typedef unsigned long long u64;

// ---------------- scratch ----------------------------------------------------
__device__ float g_xt[BATCH * L * D];           // (b,l,d)
__device__ float g_dtr[BATCH * 4 * NST * L];    // (b,k,r,l)
__device__ float g_bc[BATCH * 4 * 48 * L];      // (b,k,j,l)  j:0..23=B, 24..47=C
__device__ float g_ysum[BATCH * L * D];         // combined y (b,l,d)

__device__ __forceinline__ int map_l(int k, int l) {
    int lm = (k & 2) ? (255 - l) : l;
    if (k & 1) lm = ((lm & 15) << 4) | (lm >> 4);
    return lm;
}
__device__ __forceinline__ float silu(float x) { return x / (1.f + __expf(-x)); }

__device__ __forceinline__ u64 pk2(float lo, float hi) {
    u64 r; asm("mov.b64 %0,{%1,%2};" : "=l"(r) : "f"(lo), "f"(hi)); return r;
}
__device__ __forceinline__ void unpk2(float& lo, float& hi, u64 v) {
    asm("mov.b64 {%0,%1},%2;" : "=f"(lo), "=f"(hi) : "l"(v));
}
__device__ __forceinline__ u64 mul2(u64 a, u64 b) {
    u64 r; asm("mul.rn.f32x2 %0,%1,%2;" : "=l"(r) : "l"(a), "l"(b)); return r;
}
__device__ __forceinline__ u64 fma2(u64 a, u64 b, u64 c) {
    u64 r; asm("fma.rn.f32x2 %0,%1,%2,%3;" : "=l"(r) : "l"(a), "l"(b), "l"(c)); return r;
}
__device__ __forceinline__ unsigned f2tf(float f) {
    unsigned u; asm("cvt.rna.tf32.f32 %0,%1;" : "=r"(u) : "f"(f)); return u;
}
__device__ __forceinline__ void mma_tf32(float c[4],
                                         unsigned a0, unsigned a1, unsigned a2, unsigned a3,
                                         unsigned b0, unsigned b1) {
    asm volatile(
        "mma.sync.aligned.m16n8k8.row.col.f32.tf32.tf32.f32 "
        "{%0,%1,%2,%3},{%4,%5,%6,%7},{%8,%9},{%0,%1,%2,%3};"
        : "+f"(c[0]), "+f"(c[1]), "+f"(c[2]), "+f"(c[3])
        : "r"(a0), "r"(a1), "r"(a2), "r"(a3), "r"(b0), "r"(b1));
}

// ---------------- K1: fused rearrange + dwconv + silu + patch + BN ------------
#define FRONT_SMEM ((64 * 65 + 4 * 64 * 68 + 66 * 68) * 4)
__global__ void __launch_bounds__(512) k_front(const float* __restrict__ xin,
                                               const float* __restrict__ cw,
                                               const float* __restrict__ cb,
                                               const float* __restrict__ pw,
                                               const float* __restrict__ pb,
                                               const float* __restrict__ gam,
                                               const float* __restrict__ bet,
                                               const float* __restrict__ mn,
                                               const float* __restrict__ vr,
                                               float* __restrict__ xt,
                                               float* __restrict__ ysum) {
    extern __shared__ float fsm[];
    float* ws  = fsm;
    float* xcs = fsm + 64 * 65;
    float* ts  = xcs + 4 * 64 * 68;
    int b = blockIdx.x;
    int t = threadIdx.x;

    {
        float4* yz = (float4*)(ysum + b * 16384);
        float4 z4 = make_float4(0.f, 0.f, 0.f, 0.f);
#pragma unroll
        for (int i = 0; i < 8; i++) yz[t + i * 512] = z4;
    }
    for (int i = t; i < 4096; i += 512) ws[(i & 63) * 65 + (i >> 6)] = pw[i];

    const float* xbb = xin + b * 16384;
#pragma unroll 1
    for (int c = 0; c < 4; c++) {
        __syncthreads();
        for (int i = t; i < 66 * 68; i += 512) ts[i] = 0.f;
        __syncthreads();
        const float* xb = xbb + c * 16;
#pragma unroll
        for (int it = 0; it < 8; it++) {
            int e = it * 512 + t;
            int pq = e >> 4, ij = e & 15;
            int p = pq >> 4, q = pq & 15;
            int i2 = ij >> 2, j2 = ij & 3;
            ts[(1 + p * 4 + i2) * 68 + 1 + q * 4 + j2] = xb[pq * 64 + ij];
        }
        __syncthreads();
        float wr[9];
#pragma unroll
        for (int i = 0; i < 9; i++) wr[i] = __ldg(&cw[c * 9 + i]);
        float cbv = __ldg(&cb[c]);
        int h = t >> 3, wq = t & 7;
        float* orow = xcs + (c * 64 + h) * 68;
#pragma unroll
        for (int j = 0; j < 8; j++) {
            int wcol = wq * 8 + j;
            float acc = cbv;
#pragma unroll
            for (int di = 0; di < 3; di++)
#pragma unroll
                for (int dj = 0; dj < 3; dj++)
                    acc += ts[(h + di) * 68 + wcol + dj] * wr[di * 3 + dj];
            orow[wcol] = silu(acc);
        }
    }
    __syncthreads();

    int e = t & 63, li = t >> 6;
    float sc = __ldg(&gam[e]) * rsqrtf(__ldg(&vr[e]) + 1e-5f);
    float pbv = __ldg(&pb[e]), mnv = __ldg(&mn[e]), btv = __ldg(&bet[e]);
#pragma unroll 1
    for (int rg = 0; rg < 4; rg++) {
        int r0 = rg * 64 + li * 8;
        int rof[8];
#pragma unroll
        for (int j = 0; j < 8; j++) {
            int row = r0 + j;
            rof[j] = ((row >> 4) * 4) * 68 + (row & 15) * 4;
        }
        float acc[8];
#pragma unroll
        for (int j = 0; j < 8; j++) acc[j] = 0.f;
#pragma unroll
        for (int m4 = 0; m4 < 16; m4++) {
            int c4 = m4 >> 2, i2m = m4 & 3;
            int boff = c4 * 4352 + i2m * 68;
            float4 xv[8];
#pragma unroll
            for (int j = 0; j < 8; j++)
                xv[j] = *(const float4*)&xcs[boff + rof[j]];
#pragma unroll
            for (int dd = 0; dd < 4; dd++) {
                float wv = ws[(m4 * 4 + dd) * 65 + e];
#pragma unroll
                for (int j = 0; j < 8; j++) {
                    float v = dd == 0 ? xv[j].x : dd == 1 ? xv[j].y : dd == 2 ? xv[j].z : xv[j].w;
                    acc[j] += v * wv;
                }
            }
        }
#pragma unroll
        for (int j = 0; j < 8; j++)
            xt[(b * 256 + r0 + j) * 64 + e] = (acc[j] + pbv - mnv) * sc + btv;
    }
}

// ---------------- K3: x_dbl projection via tf32 mma ---------------------------
#define AS_STRIDE 264
#define BS_STRIDE 72
__global__ void __launch_bounds__(256, 2) k_proj(const float* __restrict__ xt,
                                                 const float* __restrict__ xpw,
                                                 float* __restrict__ dtrg,
                                                 float* __restrict__ bc) {
    extern __shared__ unsigned sm[];
    unsigned* As = sm;
    unsigned* Bs = sm + 64 * AS_STRIDE;
    int k = blockIdx.x, b = blockIdx.y;
    int t = threadIdx.x, w = t >> 5, lane = t & 31;
    int gid = lane >> 2, tig = lane & 3;
    const float* wk = xpw + k * CPROJ * 64;

    for (int i = t; i < CPROJ * 64; i += 256) {
        int c = i >> 6, kk = i & 63;
        Bs[kk * BS_STRIDE + c] = f2tf(wk[i]);
    }
    {
        int lm = map_l(k, t);
        const float4* xp = (const float4*)(xt + (b * 256 + lm) * 64);
#pragma unroll
        for (int j4 = 0; j4 < 16; j4++) {
            float4 v = __ldg(xp + j4);
            As[(4 * j4 + 0) * AS_STRIDE + t] = f2tf(v.x);
            As[(4 * j4 + 1) * AS_STRIDE + t] = f2tf(v.y);
            As[(4 * j4 + 2) * AS_STRIDE + t] = f2tf(v.z);
            As[(4 * j4 + 3) * AS_STRIDE + t] = f2tf(v.w);
        }
    }
    __syncthreads();

    int r0 = w * 32;
    unsigned a[8][2][4];
#pragma unroll
    for (int ks = 0; ks < 8; ks++) {
        int kb = ks * 8;
#pragma unroll
        for (int mi = 0; mi < 2; mi++) {
            int r = r0 + mi * 16;
            a[ks][mi][0] = As[(kb + tig) * AS_STRIDE + r + gid];
            a[ks][mi][1] = As[(kb + tig) * AS_STRIDE + r + gid + 8];
            a[ks][mi][2] = As[(kb + tig + 4) * AS_STRIDE + r + gid];
            a[ks][mi][3] = As[(kb + tig + 4) * AS_STRIDE + r + gid + 8];
        }
    }

    float* dto = dtrg + (b * 4 + k) * NST * 256;
    float* bco = bc + (b * 4 + k) * 48 * 256;
#pragma unroll
    for (int n = 0; n < 9; n++) {
        float acc0[4] = {0.f, 0.f, 0.f, 0.f};
        float acc1[4] = {0.f, 0.f, 0.f, 0.f};
#pragma unroll
        for (int ks = 0; ks < 8; ks++) {
            int kb = ks * 8;
            unsigned b0 = Bs[(kb + tig) * BS_STRIDE + n * 8 + gid];
            unsigned b1 = Bs[(kb + tig + 4) * BS_STRIDE + n * 8 + gid];
            mma_tf32(acc0, a[ks][0][0], a[ks][0][1], a[ks][0][2], a[ks][0][3], b0, b1);
            mma_tf32(acc1, a[ks][1][0], a[ks][1][1], a[ks][1][2], a[ks][1][3], b0, b1);
        }
        int c0 = n * 8 + 2 * tig;
#pragma unroll
        for (int q = 0; q < 2; q++) {
            int c = c0 + q;
            float* base = (c < 24) ? (dto + c * 256) : (bco + (c - 24) * 256);
            base[r0 + gid]          = acc0[q];
            base[r0 + gid + 8]      = acc0[q + 2];
            base[r0 + 16 + gid]     = acc1[q];
            base[r0 + 16 + gid + 8] = acc1[q + 2];
        }
    }
}
#define PROJ_SMEM ((64 * AS_STRIDE + 64 * BS_STRIDE) * 4)

// ---------------- K4: scan (R8 form, unchanged) -------------------------------
__global__ void __launch_bounds__(64) k_scan(const float* __restrict__ xt,
                                             const float* __restrict__ dtrg,
                                             const float* __restrict__ bc,
                                             const float* __restrict__ dtw_g,
                                             const float* __restrict__ alog,
                                             const float* __restrict__ dbias,
                                             const float* __restrict__ Dsv,
                                             float* __restrict__ ysum) {
    __shared__ __align__(16) float sbc[16][48];
    __shared__ __align__(16) float sdtr[NST * 16];
    __shared__ float su[16][64];
    int k = blockIdx.x, b = blockIdx.y;
    int d = threadIdx.x;
    int kd = k * 64 + d;

    float dtw[NST];
    {
        const float4* dwp = (const float4*)(dtw_g + kd * NST);
#pragma unroll
        for (int i = 0; i < 6; i++) {
            float4 v = __ldg(dwp + i);
            dtw[4 * i] = v.x; dtw[4 * i + 1] = v.y;
            dtw[4 * i + 2] = v.z; dtw[4 * i + 3] = v.w;
        }
    }
    float a0 = -__expf(__ldg(&alog[kd * NST]));
    bool chain = (a0 != 0.f);
#pragma unroll
    for (int n = 1; n < NST; n++) {
        float an = -__expf(__ldg(&alog[kd * NST + n]));
        chain = chain && (fabsf(an - (float)(n + 1) * a0) <= 1e-4f * fabsf(an));
    }
    float bias = __ldg(&dbias[kd]);
    float Dv = __ldg(&Dsv[kd]);
    int kb = b * 4 + k;
    const float* dtrp = dtrg + kb * NST * 256;
    const float* bcp = bc + kb * 48 * 256;
    const float* xrow = xt + b * 256 * 64;
    float* yb = ysum + b * 256 * 64;

    u64 h2[12];
#pragma unroll
    for (int p = 0; p < 12; p++) h2[p] = 0ull;

    for (int l0 = 0; l0 < 256; l0 += 16) {
        __syncthreads();
#pragma unroll
        for (int m = 0; m < 12; m++) {
            int idx = d * 12 + m;
            sbc[idx & 15][idx >> 4] = bcp[(idx >> 4) * 256 + l0 + (idx & 15)];
        }
#pragma unroll
        for (int m = 0; m < 6; m++) {
            int idx = d * 6 + m;
            sdtr[idx] = dtrp[(idx >> 4) * 256 + l0 + (idx & 15)];
        }
#pragma unroll
        for (int i = 0; i < 16; i++)
            su[i][d] = __ldg(&xrow[map_l(k, l0 + i) * 64 + d]);
        __syncthreads();

        float dtc[16];
        {
            u64 dt2[8];
#pragma unroll
            for (int ip = 0; ip < 8; ip++) dt2[ip] = 0ull;
#pragma unroll
            for (int r = 0; r < NST; r++) {
                u64 wp = pk2(dtw[r], dtw[r]);
#pragma unroll
                for (int q = 0; q < 4; q++) {
                    ulonglong2 v = *(const ulonglong2*)&sdtr[r * 16 + 4 * q];
                    dt2[2 * q]     = fma2(wp, v.x, dt2[2 * q]);
                    dt2[2 * q + 1] = fma2(wp, v.y, dt2[2 * q + 1]);
                }
            }
#pragma unroll
            for (int ip = 0; ip < 8; ip++) unpk2(dtc[2 * ip], dtc[2 * ip + 1], dt2[ip]);
        }

        if (chain) {
#pragma unroll 2
            for (int i = 0; i < 16; i++) {
                int l = l0 + i;
                float xv = dtc[i] + bias;
                float delta = (xv > 15.f) ? xv : __logf(1.f + __expf(xv));
                float u = su[i][d];
                float du = delta * u;
                float q = __expf(delta * a0);
                float q2s = q * q, q4s = q2s * q2s, q8s = q4s * q4s, q16s = q8s * q8s;
                u64 Q2 = pk2(q2s, q2s), Q4 = pk2(q4s, q4s);
                u64 Q8 = pk2(q8s, q8s), Q16 = pk2(q16s, q16s);
                u64 P[12];
                P[0] = pk2(q, q2s);
                P[1] = mul2(P[0], Q2);
                P[2] = mul2(P[0], Q4);  P[3] = mul2(P[1], Q4);
                P[4] = mul2(P[0], Q8);  P[5] = mul2(P[1], Q8);
                P[6] = mul2(P[2], Q8);  P[7] = mul2(P[3], Q8);
                P[8] = mul2(P[0], Q16); P[9] = mul2(P[1], Q16);
                P[10] = mul2(P[2], Q16); P[11] = mul2(P[3], Q16);
                u64 du2 = pk2(du, du);
                u64 y2a = 0ull, y2b = 0ull;
#pragma unroll
                for (int qq = 0; qq < 6; qq++) {
                    ulonglong2 Bv = *(const ulonglong2*)&sbc[i][4 * qq];
                    ulonglong2 Cv = *(const ulonglong2*)&sbc[i][24 + 4 * qq];
                    int p0 = 2 * qq, p1 = 2 * qq + 1;
                    h2[p0] = fma2(P[p0], h2[p0], mul2(du2, Bv.x));
                    y2a = fma2(h2[p0], Cv.x, y2a);
                    h2[p1] = fma2(P[p1], h2[p1], mul2(du2, Bv.y));
                    y2b = fma2(h2[p1], Cv.y, y2b);
                }
                float ylo, yhi, zlo, zhi;
                unpk2(ylo, yhi, y2a); unpk2(zlo, zhi, y2b);
                atomicAdd(&yb[map_l(k, l) * 64 + d], ylo + yhi + zlo + zhi + Dv * u);
            }
        } else {
#pragma unroll 1
            for (int i = 0; i < 16; i++) {
                int l = l0 + i;
                float xv = dtc[i] + bias;
                float delta = (xv > 15.f) ? xv : __logf(1.f + __expf(xv));
                float u = su[i][d];
                float du = delta * u;
                u64 du2 = pk2(du, du);
                u64 y2 = 0ull;
#pragma unroll
                for (int qq = 0; qq < 6; qq++) {
                    ulonglong2 Bv = *(const ulonglong2*)&sbc[i][4 * qq];
                    ulonglong2 Cv = *(const ulonglong2*)&sbc[i][24 + 4 * qq];
#pragma unroll
                    for (int s = 0; s < 2; s++) {
                        int p = 2 * qq + s;
                        float alo = -__expf(__ldg(&alog[kd * NST + 2 * p]));
                        float ahi = -__expf(__ldg(&alog[kd * NST + 2 * p + 1]));
                        u64 dA = pk2(__expf(delta * alo), __expf(delta * ahi));
                        u64 Bp = s ? Bv.y : Bv.x;
                        u64 Cp = s ? Cv.y : Cv.x;
                        h2[p] = fma2(dA, h2[p], mul2(du2, Bp));
                        y2 = fma2(h2[p], Cp, y2);
                    }
                }
                float ylo, yhi;
                unpk2(ylo, yhi, y2);
                atomicAdd(&yb[map_l(k, l) * 64 + d], ylo + yhi + Dv * u);
            }
        }
    }
}

// ---------------- K5: LN + z-gate + out_proj via tf32 mma ---------------------
// grid (2, B), 256 threads = 8 warps, each warp 16 rows.
// smem: As (X tf32 [kk][l], 64x136) | Bs (W tf32 [kk][c], 64x72) |
//       Gs (y float -> G tf32, [e][l], 64x136) | mu[128] rs[128] | gs[64] bs[64]
#define FS_AS 136
#define FS_BS 72
#define FINAL_SMEM ((64 * FS_AS + 64 * FS_BS + 64 * FS_AS + 256 + 128) * 4)
__global__ void __launch_bounds__(256) k_final(const float* __restrict__ xin,
                                               const float* __restrict__ ysum,
                                               const float* __restrict__ ipw,
                                               const float* __restrict__ lng,
                                               const float* __restrict__ lnb,
                                               const float* __restrict__ wo,
                                               float* __restrict__ out) {
    extern __shared__ float fs[];
    unsigned* As = (unsigned*)fs;                       // 64*136
    unsigned* Bs = (unsigned*)(fs + 64 * FS_AS);        // 64*72
    float* Gs    = fs + 64 * FS_AS + 64 * FS_BS;        // 64*136 (float y, then tf32 G)
    float* mus   = Gs + 64 * FS_AS;                     // 128
    float* rss   = mus + 128;                           // 128
    float* gsv   = rss + 128;                           // 64
    float* bsv   = gsv + 64;                            // 64
    int half = blockIdx.x, b = blockIdx.y;
    int t = threadIdx.x, w = t >> 5, lane = t & 31;
    int gid = lane >> 2, tig = lane & 3;
    int lbase = half * 128;

    // stage Wi (tf32): Bs[kk][e] = ipw[e*64+kk]
    for (int i = t; i < 4096; i += 256)
        Bs[(i & 63) * FS_BS + (i >> 6)] = f2tf(ipw[i]);
    // stage X rows (tf32): 2 threads per row
    {
        int lr = t >> 1, kk0 = (t & 1) * 32;
        const float4* xp = (const float4*)(xin + (b * 256 + lbase + lr) * 64 + kk0);
#pragma unroll
        for (int j4 = 0; j4 < 8; j4++) {
            float4 v = __ldg(xp + j4);
            As[(kk0 + 4 * j4 + 0) * FS_AS + lr] = f2tf(v.x);
            As[(kk0 + 4 * j4 + 1) * FS_AS + lr] = f2tf(v.y);
            As[(kk0 + 4 * j4 + 2) * FS_AS + lr] = f2tf(v.z);
            As[(kk0 + 4 * j4 + 3) * FS_AS + lr] = f2tf(v.w);
        }
    }
    // stage y rows (float) into Gs[e][l]
    {
        const float* yb = ysum + (b * 256 + lbase) * 64;
#pragma unroll
        for (int i = 0; i < 32; i++) {
            int idx = i * 256 + t;
            Gs[(idx & 63) * FS_AS + (idx >> 6)] = yb[idx];
        }
    }
    if (t < 64) { gsv[t] = lng[t]; bsv[t] = lnb[t]; }
    __syncthreads();
    // LN stats per row (two-pass, exact reference semantics)
    if (t < 128) {
        float s = 0.f;
#pragma unroll
        for (int e = 0; e < 64; e++) s += Gs[e * FS_AS + t];
        float mu = s * (1.f / 64.f);
        float v = 0.f;
#pragma unroll
        for (int e = 0; e < 64; e++) {
            float dd = Gs[e * FS_AS + t] - mu;
            v += dd * dd;
        }
        mus[t] = mu;
        rss[t] = rsqrtf(v * (1.f / 64.f) + 1e-5f);
    }
    __syncthreads();

    int r0 = w * 16;
    unsigned a[8][4];
#pragma unroll
    for (int ks = 0; ks < 8; ks++) {
        int kb = ks * 8;
        a[ks][0] = As[(kb + tig) * FS_AS + r0 + gid];
        a[ks][1] = As[(kb + tig) * FS_AS + r0 + gid + 8];
        a[ks][2] = As[(kb + tig + 4) * FS_AS + r0 + gid];
        a[ks][3] = As[(kb + tig + 4) * FS_AS + r0 + gid + 8];
    }
    // GEMM1: z = X @ Wi^T, then transform into G (tf32) in place
    unsigned* Gt = (unsigned*)Gs;
#pragma unroll
    for (int n = 0; n < 8; n++) {
        float acc[4] = {0.f, 0.f, 0.f, 0.f};
#pragma unroll
        for (int ks = 0; ks < 8; ks++) {
            int kb = ks * 8;
            unsigned b0 = Bs[(kb + tig) * FS_BS + n * 8 + gid];
            unsigned b1 = Bs[(kb + tig + 4) * FS_BS + n * 8 + gid];
            mma_tf32(acc, a[ks][0], a[ks][1], a[ks][2], a[ks][3], b0, b1);
        }
        int c0 = n * 8 + 2 * tig;
#pragma unroll
        for (int q = 0; q < 4; q++) {
            int c = c0 + (q & 1);
            int r = r0 + gid + ((q >> 1) * 8);
            float z = silu(acc[q]);
            float y = Gs[c * FS_AS + r];
            float g = ((y - mus[r]) * rss[r] * gsv[c] + bsv[c]) * z;
            Gt[c * FS_AS + r] = f2tf(g);
        }
    }
    __syncthreads();
    // restage Wo: Bs[kk][dd] = wo[dd*64+kk]
    for (int i = t; i < 4096; i += 256)
        Bs[(i & 63) * FS_BS + (i >> 6)] = f2tf(wo[i]);
    __syncthreads();
    // GEMM2: out = G @ Wo^T
#pragma unroll
    for (int ks = 0; ks < 8; ks++) {
        int kb = ks * 8;
        a[ks][0] = Gt[(kb + tig) * FS_AS + r0 + gid];
        a[ks][1] = Gt[(kb + tig) * FS_AS + r0 + gid + 8];
        a[ks][2] = Gt[(kb + tig + 4) * FS_AS + r0 + gid];
        a[ks][3] = Gt[(kb + tig + 4) * FS_AS + r0 + gid + 8];
    }
    float* ob = out + (b * 256 + lbase) * 64;
#pragma unroll
    for (int n = 0; n < 8; n++) {
        float acc[4] = {0.f, 0.f, 0.f, 0.f};
#pragma unroll
        for (int ks = 0; ks < 8; ks++) {
            int kb = ks * 8;
            unsigned b0 = Bs[(kb + tig) * FS_BS + n * 8 + gid];
            unsigned b1 = Bs[(kb + tig + 4) * FS_BS + n * 8 + gid];
            mma_tf32(acc, a[ks][0], a[ks][1], a[ks][2], a[ks][3], b0, b1);
        }
        int c0 = n * 8 + 2 * tig;
#pragma unroll
        for (int q = 0; q < 4; q++) {
            int c = c0 + (q & 1);
            int r = r0 + gid + ((q >> 1) * 8);
            ob[r * 64 + c] = acc[q];
        }
    }
}

// ---------------- launch ------------------------------------------------------
extern "C" void kernel_launch(void* const* d_in, const int* in_sizes, int n_in,
                              void* d_out, int out_size) {
    const float* x_in   = (const float*)d_in[0];
    const float* ipw    = (const float*)d_in[1];
    const float* conv_w = (const float*)d_in[2];
    const float* conv_b = (const float*)d_in[3];
    const float* patch_w= (const float*)d_in[4];
    const float* patch_b= (const float*)d_in[5];
    const float* bn_g   = (const float*)d_in[6];
    const float* bn_b   = (const float*)d_in[7];
    const float* bn_m   = (const float*)d_in[8];
    const float* bn_v   = (const float*)d_in[9];
    const float* xpw    = (const float*)d_in[10];
    const float* dtw    = (const float*)d_in[11];
    const float* dtb    = (const float*)d_in[12];
    const float* alog   = (const float*)d_in[13];
    const float* Dsv    = (const float*)d_in[14];
    const float* lng    = (const float*)d_in[15];
    const float* lnb    = (const float*)d_in[16];
    const float* wo     = (const float*)d_in[17];
    float* out = (float*)d_out;

    float *xt, *dtrg, *bcv, *ysum;
    cudaGetSymbolAddress((void**)&xt,   g_xt);
    cudaGetSymbolAddress((void**)&dtrg, g_dtr);
    cudaGetSymbolAddress((void**)&bcv,  g_bc);
    cudaGetSymbolAddress((void**)&ysum, g_ysum);

    cudaFuncSetAttribute(k_front, cudaFuncAttributeMaxDynamicSharedMemorySize,
                         FRONT_SMEM);
    cudaFuncSetAttribute(k_proj, cudaFuncAttributeMaxDynamicSharedMemorySize,
                         PROJ_SMEM);
    cudaFuncSetAttribute(k_final, cudaFuncAttributeMaxDynamicSharedMemorySize,
                         FINAL_SMEM);

    k_front<<<BATCH, 512, FRONT_SMEM>>>(x_in, conv_w, conv_b, patch_w, patch_b,
                                        bn_g, bn_b, bn_m, bn_v, xt, ysum);
    k_proj<<<dim3(4, BATCH), 256, PROJ_SMEM>>>(xt, xpw, dtrg, bcv);
    k_scan<<<dim3(4, BATCH), 64>>>(xt, dtrg, bcv, dtw, alog, dtb, Dsv, ysum);
    k_final<<<dim3(2, BATCH), 256, FINAL_SMEM>>>(x_in, ysum, ipw, lng, lnb, wo, out);
}

// round 15
// speedup vs baseline: 1.4231x; 1.0107x over previous
#include <cuda_runtime.h>
#include <cuda_bf16.h>

#define BATCH 256
#define L 256
#define D 64
#define NST 24
#define CPROJ 72   // DT_RANK + 2*NST

typedef unsigned long long u64;

// ---------------- scratch ----------------------------------------------------
__device__ float g_xt[BATCH * L * D];           // (b,l,d)
__device__ float g_dtr[BATCH * 4 * NST * L];    // (b,k,r,l)
__device__ float g_bc[BATCH * 4 * 48 * L];      // (b,k,j,l)  j:0..23=B, 24..47=C
__device__ float g_ysum[BATCH * L * D];         // combined y (b,l,d)

__device__ __forceinline__ int map_l(int k, int l) {
    int lm = (k & 2) ? (255 - l) : l;
    if (k & 1) lm = ((lm & 15) << 4) | (lm >> 4);
    return lm;
}
__device__ __forceinline__ float silu(float x) { return x / (1.f + __expf(-x)); }

__device__ __forceinline__ u64 pk2(float lo, float hi) {
    u64 r; asm("mov.b64 %0,{%1,%2};" : "=l"(r) : "f"(lo), "f"(hi)); return r;
}
__device__ __forceinline__ void unpk2(float& lo, float& hi, u64 v) {
    asm("mov.b64 {%0,%1},%2;" : "=f"(lo), "=f"(hi) : "l"(v));
}
__device__ __forceinline__ u64 mul2(u64 a, u64 b) {
    u64 r; asm("mul.rn.f32x2 %0,%1,%2;" : "=l"(r) : "l"(a), "l"(b)); return r;
}
__device__ __forceinline__ u64 fma2(u64 a, u64 b, u64 c) {
    u64 r; asm("fma.rn.f32x2 %0,%1,%2,%3;" : "=l"(r) : "l"(a), "l"(b), "l"(c)); return r;
}
__device__ __forceinline__ unsigned f2tf(float f) {
    unsigned u; asm("cvt.rna.tf32.f32 %0,%1;" : "=r"(u) : "f"(f)); return u;
}
__device__ __forceinline__ void mma_tf32(float c[4],
                                         unsigned a0, unsigned a1, unsigned a2, unsigned a3,
                                         unsigned b0, unsigned b1) {
    asm volatile(
        "mma.sync.aligned.m16n8k8.row.col.f32.tf32.tf32.f32 "
        "{%0,%1,%2,%3},{%4,%5,%6,%7},{%8,%9},{%0,%1,%2,%3};"
        : "+f"(c[0]), "+f"(c[1]), "+f"(c[2]), "+f"(c[3])
        : "r"(a0), "r"(a1), "r"(a2), "r"(a3), "r"(b0), "r"(b1));
}

// ---------------- K1: fused rearrange + dwconv + silu + patch + BN ------------
#define FRONT_SMEM ((64 * 65 + 4 * 64 * 68 + 66 * 68) * 4)
__global__ void __launch_bounds__(512) k_front(const float* __restrict__ xin,
                                               const float* __restrict__ cw,
                                               const float* __restrict__ cb,
                                               const float* __restrict__ pw,
                                               const float* __restrict__ pb,
                                               const float* __restrict__ gam,
                                               const float* __restrict__ bet,
                                               const float* __restrict__ mn,
                                               const float* __restrict__ vr,
                                               float* __restrict__ xt,
                                               float* __restrict__ ysum) {
    extern __shared__ float fsm[];
    float* ws  = fsm;
    float* xcs = fsm + 64 * 65;
    float* ts  = xcs + 4 * 64 * 68;
    int b = blockIdx.x;
    int t = threadIdx.x;

    {
        float4* yz = (float4*)(ysum + b * 16384);
        float4 z4 = make_float4(0.f, 0.f, 0.f, 0.f);
#pragma unroll
        for (int i = 0; i < 8; i++) yz[t + i * 512] = z4;
    }
    for (int i = t; i < 4096; i += 512) ws[(i & 63) * 65 + (i >> 6)] = pw[i];

    const float* xbb = xin + b * 16384;
#pragma unroll 1
    for (int c = 0; c < 4; c++) {
        __syncthreads();
        for (int i = t; i < 66 * 68; i += 512) ts[i] = 0.f;
        __syncthreads();
        const float* xb = xbb + c * 16;
#pragma unroll
        for (int it = 0; it < 8; it++) {
            int e = it * 512 + t;
            int pq = e >> 4, ij = e & 15;
            int p = pq >> 4, q = pq & 15;
            int i2 = ij >> 2, j2 = ij & 3;
            ts[(1 + p * 4 + i2) * 68 + 1 + q * 4 + j2] = xb[pq * 64 + ij];
        }
        __syncthreads();
        float wr[9];
#pragma unroll
        for (int i = 0; i < 9; i++) wr[i] = __ldg(&cw[c * 9 + i]);
        float cbv = __ldg(&cb[c]);
        int h = t >> 3, wq = t & 7;
        float* orow = xcs + (c * 64 + h) * 68;
#pragma unroll
        for (int j = 0; j < 8; j++) {
            int wcol = wq * 8 + j;
            float acc = cbv;
#pragma unroll
            for (int di = 0; di < 3; di++)
#pragma unroll
                for (int dj = 0; dj < 3; dj++)
                    acc += ts[(h + di) * 68 + wcol + dj] * wr[di * 3 + dj];
            orow[wcol] = silu(acc);
        }
    }
    __syncthreads();

    int e = t & 63, li = t >> 6;
    float sc = __ldg(&gam[e]) * rsqrtf(__ldg(&vr[e]) + 1e-5f);
    float pbv = __ldg(&pb[e]), mnv = __ldg(&mn[e]), btv = __ldg(&bet[e]);
#pragma unroll 1
    for (int rg = 0; rg < 4; rg++) {
        int r0 = rg * 64 + li * 8;
        int rof[8];
#pragma unroll
        for (int j = 0; j < 8; j++) {
            int row = r0 + j;
            rof[j] = ((row >> 4) * 4) * 68 + (row & 15) * 4;
        }
        float acc[8];
#pragma unroll
        for (int j = 0; j < 8; j++) acc[j] = 0.f;
#pragma unroll
        for (int m4 = 0; m4 < 16; m4++) {
            int c4 = m4 >> 2, i2m = m4 & 3;
            int boff = c4 * 4352 + i2m * 68;
            float4 xv[8];
#pragma unroll
            for (int j = 0; j < 8; j++)
                xv[j] = *(const float4*)&xcs[boff + rof[j]];
#pragma unroll
            for (int dd = 0; dd < 4; dd++) {
                float wv = ws[(m4 * 4 + dd) * 65 + e];
#pragma unroll
                for (int j = 0; j < 8; j++) {
                    float v = dd == 0 ? xv[j].x : dd == 1 ? xv[j].y : dd == 2 ? xv[j].z : xv[j].w;
                    acc[j] += v * wv;
                }
            }
        }
#pragma unroll
        for (int j = 0; j < 8; j++)
            xt[(b * 256 + r0 + j) * 64 + e] = (acc[j] + pbv - mnv) * sc + btv;
    }
}

// ---------------- K3: x_dbl projection via tf32 mma, 2 CTAs per (k,b) --------
#define AS_STRIDE 136
#define BS_STRIDE 72
__global__ void __launch_bounds__(256, 3) k_proj(const float* __restrict__ xt,
                                                 const float* __restrict__ xpw,
                                                 float* __restrict__ dtrg,
                                                 float* __restrict__ bc) {
    extern __shared__ unsigned sm[];
    unsigned* As = sm;                     // 64 * 136
    unsigned* Bs = sm + 64 * AS_STRIDE;    // 64 * 72
    int kh = blockIdx.x, b = blockIdx.y;
    int k = kh & 3, half = kh >> 2;
    int t = threadIdx.x, w = t >> 5, lane = t & 31;
    int gid = lane >> 2, tig = lane & 3;
    const float* wk = xpw + k * CPROJ * 64;

    for (int i = t; i < CPROJ * 64; i += 256) {
        int c = i >> 6, kk = i & 63;
        Bs[kk * BS_STRIDE + c] = f2tf(wk[i]);
    }
    {
        int lr = t >> 1;
        int kk0 = (t & 1) * 32;
        int lm = map_l(k, half * 128 + lr);
        const float4* xp = (const float4*)(xt + (b * 256 + lm) * 64 + kk0);
#pragma unroll
        for (int j4 = 0; j4 < 8; j4++) {
            float4 v = __ldg(xp + j4);
            As[(kk0 + 4 * j4 + 0) * AS_STRIDE + lr] = f2tf(v.x);
            As[(kk0 + 4 * j4 + 1) * AS_STRIDE + lr] = f2tf(v.y);
            As[(kk0 + 4 * j4 + 2) * AS_STRIDE + lr] = f2tf(v.z);
            As[(kk0 + 4 * j4 + 3) * AS_STRIDE + lr] = f2tf(v.w);
        }
    }
    __syncthreads();

    int r0 = w * 16;
    unsigned a[8][4];
#pragma unroll
    for (int ks = 0; ks < 8; ks++) {
        int kb = ks * 8;
        a[ks][0] = As[(kb + tig) * AS_STRIDE + r0 + gid];
        a[ks][1] = As[(kb + tig) * AS_STRIDE + r0 + gid + 8];
        a[ks][2] = As[(kb + tig + 4) * AS_STRIDE + r0 + gid];
        a[ks][3] = As[(kb + tig + 4) * AS_STRIDE + r0 + gid + 8];
    }

    float* dto = dtrg + (b * 4 + k) * NST * 256;
    float* bco = bc + (b * 4 + k) * 48 * 256;
    int rg = half * 128 + r0 + gid;
#pragma unroll
    for (int n = 0; n < 9; n++) {
        float acc[4] = {0.f, 0.f, 0.f, 0.f};
#pragma unroll
        for (int ks = 0; ks < 8; ks++) {
            int kb = ks * 8;
            unsigned b0 = Bs[(kb + tig) * BS_STRIDE + n * 8 + gid];
            unsigned b1 = Bs[(kb + tig + 4) * BS_STRIDE + n * 8 + gid];
            mma_tf32(acc, a[ks][0], a[ks][1], a[ks][2], a[ks][3], b0, b1);
        }
        int c0 = n * 8 + 2 * tig;
#pragma unroll
        for (int q = 0; q < 2; q++) {
            int c = c0 + q;
            float* base = (c < 24) ? (dto + c * 256) : (bco + (c - 24) * 256);
            base[rg]     = acc[q];
            base[rg + 8] = acc[q + 2];
        }
    }
}
#define PROJ_SMEM ((64 * AS_STRIDE + 64 * BS_STRIDE) * 4)

// ---------------- K4: scan (R8 form, unchanged) -------------------------------
__global__ void __launch_bounds__(64) k_scan(const float* __restrict__ xt,
                                             const float* __restrict__ dtrg,
                                             const float* __restrict__ bc,
                                             const float* __restrict__ dtw_g,
                                             const float* __restrict__ alog,
                                             const float* __restrict__ dbias,
                                             const float* __restrict__ Dsv,
                                             float* __restrict__ ysum) {
    __shared__ __align__(16) float sbc[16][48];
    __shared__ __align__(16) float sdtr[NST * 16];
    __shared__ float su[16][64];
    int k = blockIdx.x, b = blockIdx.y;
    int d = threadIdx.x;
    int kd = k * 64 + d;

    float dtw[NST];
    {
        const float4* dwp = (const float4*)(dtw_g + kd * NST);
#pragma unroll
        for (int i = 0; i < 6; i++) {
            float4 v = __ldg(dwp + i);
            dtw[4 * i] = v.x; dtw[4 * i + 1] = v.y;
            dtw[4 * i + 2] = v.z; dtw[4 * i + 3] = v.w;
        }
    }
    float a0 = -__expf(__ldg(&alog[kd * NST]));
    bool chain = (a0 != 0.f);
#pragma unroll
    for (int n = 1; n < NST; n++) {
        float an = -__expf(__ldg(&alog[kd * NST + n]));
        chain = chain && (fabsf(an - (float)(n + 1) * a0) <= 1e-4f * fabsf(an));
    }
    float bias = __ldg(&dbias[kd]);
    float Dv = __ldg(&Dsv[kd]);
    int kb = b * 4 + k;
    const float* dtrp = dtrg + kb * NST * 256;
    const float* bcp = bc + kb * 48 * 256;
    const float* xrow = xt + b * 256 * 64;
    float* yb = ysum + b * 256 * 64;

    u64 h2[12];
#pragma unroll
    for (int p = 0; p < 12; p++) h2[p] = 0ull;

    for (int l0 = 0; l0 < 256; l0 += 16) {
        __syncthreads();
#pragma unroll
        for (int m = 0; m < 12; m++) {
            int idx = d * 12 + m;
            sbc[idx & 15][idx >> 4] = bcp[(idx >> 4) * 256 + l0 + (idx & 15)];
        }
#pragma unroll
        for (int m = 0; m < 6; m++) {
            int idx = d * 6 + m;
            sdtr[idx] = dtrp[(idx >> 4) * 256 + l0 + (idx & 15)];
        }
#pragma unroll
        for (int i = 0; i < 16; i++)
            su[i][d] = __ldg(&xrow[map_l(k, l0 + i) * 64 + d]);
        __syncthreads();

        float dtc[16];
        {
            u64 dt2[8];
#pragma unroll
            for (int ip = 0; ip < 8; ip++) dt2[ip] = 0ull;
#pragma unroll
            for (int r = 0; r < NST; r++) {
                u64 wp = pk2(dtw[r], dtw[r]);
#pragma unroll
                for (int q = 0; q < 4; q++) {
                    ulonglong2 v = *(const ulonglong2*)&sdtr[r * 16 + 4 * q];
                    dt2[2 * q]     = fma2(wp, v.x, dt2[2 * q]);
                    dt2[2 * q + 1] = fma2(wp, v.y, dt2[2 * q + 1]);
                }
            }
#pragma unroll
            for (int ip = 0; ip < 8; ip++) unpk2(dtc[2 * ip], dtc[2 * ip + 1], dt2[ip]);
        }

        if (chain) {
#pragma unroll 2
            for (int i = 0; i < 16; i++) {
                int l = l0 + i;
                float xv = dtc[i] + bias;
                float delta = (xv > 15.f) ? xv : __logf(1.f + __expf(xv));
                float u = su[i][d];
                float du = delta * u;
                float q = __expf(delta * a0);
                float q2s = q * q, q4s = q2s * q2s, q8s = q4s * q4s, q16s = q8s * q8s;
                u64 Q2 = pk2(q2s, q2s), Q4 = pk2(q4s, q4s);
                u64 Q8 = pk2(q8s, q8s), Q16 = pk2(q16s, q16s);
                u64 P[12];
                P[0] = pk2(q, q2s);
                P[1] = mul2(P[0], Q2);
                P[2] = mul2(P[0], Q4);  P[3] = mul2(P[1], Q4);
                P[4] = mul2(P[0], Q8);  P[5] = mul2(P[1], Q8);
                P[6] = mul2(P[2], Q8);  P[7] = mul2(P[3], Q8);
                P[8] = mul2(P[0], Q16); P[9] = mul2(P[1], Q16);
                P[10] = mul2(P[2], Q16); P[11] = mul2(P[3], Q16);
                u64 du2 = pk2(du, du);
                u64 y2a = 0ull, y2b = 0ull;
#pragma unroll
                for (int qq = 0; qq < 6; qq++) {
                    ulonglong2 Bv = *(const ulonglong2*)&sbc[i][4 * qq];
                    ulonglong2 Cv = *(const ulonglong2*)&sbc[i][24 + 4 * qq];
                    int p0 = 2 * qq, p1 = 2 * qq + 1;
                    h2[p0] = fma2(P[p0], h2[p0], mul2(du2, Bv.x));
                    y2a = fma2(h2[p0], Cv.x, y2a);
                    h2[p1] = fma2(P[p1], h2[p1], mul2(du2, Bv.y));
                    y2b = fma2(h2[p1], Cv.y, y2b);
                }
                float ylo, yhi, zlo, zhi;
                unpk2(ylo, yhi, y2a); unpk2(zlo, zhi, y2b);
                atomicAdd(&yb[map_l(k, l) * 64 + d], ylo + yhi + zlo + zhi + Dv * u);
            }
        } else {
#pragma unroll 1
            for (int i = 0; i < 16; i++) {
                int l = l0 + i;
                float xv = dtc[i] + bias;
                float delta = (xv > 15.f) ? xv : __logf(1.f + __expf(xv));
                float u = su[i][d];
                float du = delta * u;
                u64 du2 = pk2(du, du);
                u64 y2 = 0ull;
#pragma unroll
                for (int qq = 0; qq < 6; qq++) {
                    ulonglong2 Bv = *(const ulonglong2*)&sbc[i][4 * qq];
                    ulonglong2 Cv = *(const ulonglong2*)&sbc[i][24 + 4 * qq];
#pragma unroll
                    for (int s = 0; s < 2; s++) {
                        int p = 2 * qq + s;
                        float alo = -__expf(__ldg(&alog[kd * NST + 2 * p]));
                        float ahi = -__expf(__ldg(&alog[kd * NST + 2 * p + 1]));
                        u64 dA = pk2(__expf(delta * alo), __expf(delta * ahi));
                        u64 Bp = s ? Bv.y : Bv.x;
                        u64 Cp = s ? Cv.y : Cv.x;
                        h2[p] = fma2(dA, h2[p], mul2(du2, Bp));
                        y2 = fma2(h2[p], Cp, y2);
                    }
                }
                float ylo, yhi;
                unpk2(ylo, yhi, y2);
                atomicAdd(&yb[map_l(k, l) * 64 + d], ylo + yhi + Dv * u);
            }
        }
    }
}

// ---------------- K5: LN + z-gate + out_proj via tf32 mma ---------------------
// grid (2, B), 256 threads = 8 warps. Separate Wi/Wo buffers (one less sync).
#define FS_AS 136
#define FS_BS 72
#define FINAL_SMEM ((64 * FS_AS + 2 * 64 * FS_BS + 64 * FS_AS + 256 + 128) * 4)
__global__ void __launch_bounds__(256) k_final(const float* __restrict__ xin,
                                               const float* __restrict__ ysum,
                                               const float* __restrict__ ipw,
                                               const float* __restrict__ lng,
                                               const float* __restrict__ lnb,
                                               const float* __restrict__ wo,
                                               float* __restrict__ out) {
    extern __shared__ float fs[];
    unsigned* As  = (unsigned*)fs;                                // 64*136
    unsigned* Bwi = (unsigned*)(fs + 64 * FS_AS);                 // 64*72
    unsigned* Bwo = Bwi + 64 * FS_BS;                             // 64*72
    float* Gs     = fs + 64 * FS_AS + 2 * 64 * FS_BS;             // 64*136
    float* mus    = Gs + 64 * FS_AS;                              // 128
    float* rss    = mus + 128;                                    // 128
    float* gsv    = rss + 128;                                    // 64
    float* bsv    = gsv + 64;                                     // 64
    int half = blockIdx.x, b = blockIdx.y;
    int t = threadIdx.x, w = t >> 5, lane = t & 31;
    int gid = lane >> 2, tig = lane & 3;
    int lbase = half * 128;

    for (int i = t; i < 4096; i += 256) {
        Bwi[(i & 63) * FS_BS + (i >> 6)] = f2tf(ipw[i]);
        Bwo[(i & 63) * FS_BS + (i >> 6)] = f2tf(wo[i]);
    }
    {
        int lr = t >> 1, kk0 = (t & 1) * 32;
        const float4* xp = (const float4*)(xin + (b * 256 + lbase + lr) * 64 + kk0);
#pragma unroll
        for (int j4 = 0; j4 < 8; j4++) {
            float4 v = __ldg(xp + j4);
            As[(kk0 + 4 * j4 + 0) * FS_AS + lr] = f2tf(v.x);
            As[(kk0 + 4 * j4 + 1) * FS_AS + lr] = f2tf(v.y);
            As[(kk0 + 4 * j4 + 2) * FS_AS + lr] = f2tf(v.z);
            As[(kk0 + 4 * j4 + 3) * FS_AS + lr] = f2tf(v.w);
        }
    }
    {
        const float* yb = ysum + (b * 256 + lbase) * 64;
#pragma unroll
        for (int i = 0; i < 32; i++) {
            int idx = i * 256 + t;
            Gs[(idx & 63) * FS_AS + (idx >> 6)] = yb[idx];
        }
    }
    if (t < 64) { gsv[t] = lng[t]; bsv[t] = lnb[t]; }
    __syncthreads();
    if (t < 128) {
        float s = 0.f;
#pragma unroll
        for (int e = 0; e < 64; e++) s += Gs[e * FS_AS + t];
        float mu = s * (1.f / 64.f);
        float v = 0.f;
#pragma unroll
        for (int e = 0; e < 64; e++) {
            float dd = Gs[e * FS_AS + t] - mu;
            v += dd * dd;
        }
        mus[t] = mu;
        rss[t] = rsqrtf(v * (1.f / 64.f) + 1e-5f);
    }
    __syncthreads();

    int r0 = w * 16;
    unsigned a[8][4];
#pragma unroll
    for (int ks = 0; ks < 8; ks++) {
        int kb = ks * 8;
        a[ks][0] = As[(kb + tig) * FS_AS + r0 + gid];
        a[ks][1] = As[(kb + tig) * FS_AS + r0 + gid + 8];
        a[ks][2] = As[(kb + tig + 4) * FS_AS + r0 + gid];
        a[ks][3] = As[(kb + tig + 4) * FS_AS + r0 + gid + 8];
    }
    unsigned* Gt = (unsigned*)Gs;
#pragma unroll
    for (int n = 0; n < 8; n++) {
        float acc[4] = {0.f, 0.f, 0.f, 0.f};
#pragma unroll
        for (int ks = 0; ks < 8; ks++) {
            int kb = ks * 8;
            unsigned b0 = Bwi[(kb + tig) * FS_BS + n * 8 + gid];
            unsigned b1 = Bwi[(kb + tig + 4) * FS_BS + n * 8 + gid];
            mma_tf32(acc, a[ks][0], a[ks][1], a[ks][2], a[ks][3], b0, b1);
        }
        int c0 = n * 8 + 2 * tig;
#pragma unroll
        for (int q = 0; q < 4; q++) {
            int c = c0 + (q & 1);
            int r = r0 + gid + ((q >> 1) * 8);
            float z = silu(acc[q]);
            float y = Gs[c * FS_AS + r];
            float g = ((y - mus[r]) * rss[r] * gsv[c] + bsv[c]) * z;
            Gt[c * FS_AS + r] = f2tf(g);
        }
    }
    __syncthreads();
#pragma unroll
    for (int ks = 0; ks < 8; ks++) {
        int kb = ks * 8;
        a[ks][0] = Gt[(kb + tig) * FS_AS + r0 + gid];
        a[ks][1] = Gt[(kb + tig) * FS_AS + r0 + gid + 8];
        a[ks][2] = Gt[(kb + tig + 4) * FS_AS + r0 + gid];
        a[ks][3] = Gt[(kb + tig + 4) * FS_AS + r0 + gid + 8];
    }
    float* ob = out + (b * 256 + lbase) * 64;
#pragma unroll
    for (int n = 0; n < 8; n++) {
        float acc[4] = {0.f, 0.f, 0.f, 0.f};
#pragma unroll
        for (int ks = 0; ks < 8; ks++) {
            int kb = ks * 8;
            unsigned b0 = Bwo[(kb + tig) * FS_BS + n * 8 + gid];
            unsigned b1 = Bwo[(kb + tig + 4) * FS_BS + n * 8 + gid];
            mma_tf32(acc, a[ks][0], a[ks][1], a[ks][2], a[ks][3], b0, b1);
        }
        int c0 = n * 8 + 2 * tig;
        int r = r0 + gid;
        *(float2*)&ob[r * 64 + c0]       = make_float2(acc[0], acc[1]);
        *(float2*)&ob[(r + 8) * 64 + c0] = make_float2(acc[2], acc[3]);
    }
}

// ---------------- launch ------------------------------------------------------
extern "C" void kernel_launch(void* const* d_in, const int* in_sizes, int n_in,
                              void* d_out, int out_size) {
    const float* x_in   = (const float*)d_in[0];
    const float* ipw    = (const float*)d_in[1];
    const float* conv_w = (const float*)d_in[2];
    const float* conv_b = (const float*)d_in[3];
    const float* patch_w= (const float*)d_in[4];
    const float* patch_b= (const float*)d_in[5];
    const float* bn_g   = (const float*)d_in[6];
    const float* bn_b   = (const float*)d_in[7];
    const float* bn_m   = (const float*)d_in[8];
    const float* bn_v   = (const float*)d_in[9];
    const float* xpw    = (const float*)d_in[10];
    const float* dtw    = (const float*)d_in[11];
    const float* dtb    = (const float*)d_in[12];
    const float* alog   = (const float*)d_in[13];
    const float* Dsv    = (const float*)d_in[14];
    const float* lng    = (const float*)d_in[15];
    const float* lnb    = (const float*)d_in[16];
    const float* wo     = (const float*)d_in[17];
    float* out = (float*)d_out;

    float *xt, *dtrg, *bcv, *ysum;
    cudaGetSymbolAddress((void**)&xt,   g_xt);
    cudaGetSymbolAddress((void**)&dtrg, g_dtr);
    cudaGetSymbolAddress((void**)&bcv,  g_bc);
    cudaGetSymbolAddress((void**)&ysum, g_ysum);

    cudaFuncSetAttribute(k_front, cudaFuncAttributeMaxDynamicSharedMemorySize,
                         FRONT_SMEM);
    cudaFuncSetAttribute(k_proj, cudaFuncAttributeMaxDynamicSharedMemorySize,
                         PROJ_SMEM);
    cudaFuncSetAttribute(k_final, cudaFuncAttributeMaxDynamicSharedMemorySize,
                         FINAL_SMEM);

    k_front<<<BATCH, 512, FRONT_SMEM>>>(x_in, conv_w, conv_b, patch_w, patch_b,
                                        bn_g, bn_b, bn_m, bn_v, xt, ysum);
    k_proj<<<dim3(8, BATCH), 256, PROJ_SMEM>>>(xt, xpw, dtrg, bcv);
    k_scan<<<dim3(4, BATCH), 64>>>(xt, dtrg, bcv, dtw, alog, dtb, Dsv, ysum);
    k_final<<<dim3(2, BATCH), 256, FINAL_SMEM>>>(x_in, ysum, ipw, lng, lnb, wo, out);
}